// round 14
// baseline (speedup 1.0000x reference)
#include <cuda_runtime.h>
#include <cuda_fp16.h>
#include <math.h>
#include <stdint.h>

#define BB 4
#define SS 1024
#define DD 1024
#define HH 16
#define FF 4096
#define DHD 64
#define NG (BB*HH)
#define MR (BB*SS)

// ---------------- scratch (static device globals; no allocation) -------------
__device__ float g_tmp[MR*DD];
__device__ float g_h[MR*DD];
__device__ float g_btab[(2*SS-1)*HH];

__device__ __half g_xh[MR*DD],  g_xl[MR*DD];
__device__ __half g_qh[MR*DD],  g_ql[MR*DD];
__device__ __half g_kh[MR*DD],  g_kl[MR*DD];
__device__ __half g_v16[MR*DD];
__device__ __half g_att16[MR*DD];
__device__ __half g_h16[MR*DD];
__device__ __half g_f16[(size_t)MR*FF];
__device__ __half g_wqh[DD*DD], g_wql[DD*DD];
__device__ __half g_wkh[DD*DD], g_wkl[DD*DD];
__device__ __half g_wvh[DD*DD], g_wvl[DD*DD];
__device__ __half g_woh[DD*DD], g_wol[DD*DD];
__device__ __half g_w1h[(size_t)DD*FF], g_w1l[(size_t)DD*FF];
__device__ __half g_w2h[(size_t)FF*DD], g_w2l[(size_t)FF*DD];

// ---------------- PTX helpers ------------------------------------------------
#define SWZ(o) ((o) ^ (((o) >> 3) & 0x70))

__device__ __forceinline__ uint32_t s2u(const void* p){
    uint32_t a;
    asm("{ .reg .u64 t; cvta.to.shared.u64 t, %1; cvt.u32.u64 %0, t; }"
        : "=r"(a) : "l"(p));
    return a;
}
__device__ __forceinline__ void cp16(uint32_t d, const void* s){
    asm volatile("cp.async.cg.shared.global [%0], [%1], 16;" :: "r"(d), "l"(s));
}
__device__ __forceinline__ void ldm4(uint32_t* r, uint32_t a){
    asm volatile("ldmatrix.sync.aligned.m8n8.x4.shared.b16 {%0,%1,%2,%3}, [%4];"
        : "=r"(r[0]), "=r"(r[1]), "=r"(r[2]), "=r"(r[3]) : "r"(a));
}
__device__ __forceinline__ void ldm4t(uint32_t* r, uint32_t a){
    asm volatile("ldmatrix.sync.aligned.m8n8.x4.trans.shared.b16 {%0,%1,%2,%3}, [%4];"
        : "=r"(r[0]), "=r"(r[1]), "=r"(r[2]), "=r"(r[3]) : "r"(a));
}
__device__ __forceinline__ void mma_hf(float* c, const uint32_t* a,
                                       uint32_t b0, uint32_t b1){
    asm volatile("mma.sync.aligned.m16n8k16.row.col.f32.f16.f16.f32 "
        "{%0,%1,%2,%3}, {%4,%5,%6,%7}, {%8,%9}, {%0,%1,%2,%3};"
        : "+f"(c[0]), "+f"(c[1]), "+f"(c[2]), "+f"(c[3])
        : "r"(a[0]), "r"(a[1]), "r"(a[2]), "r"(a[3]), "r"(b0), "r"(b1));
}
__device__ __forceinline__ uint32_t h2u(__half2 v){ return *(uint32_t*)&v; }

__device__ __forceinline__ __half2 split_h2(float a, float b, __half2* lo){
    __half h0 = __float2half_rn(a), h1 = __float2half_rn(b);
    *lo = __halves2half2(__float2half_rn(a - __half2float(h0)),
                         __float2half_rn(b - __half2float(h1)));
    return __halves2half2(h0, h1);
}

// ---------------- relative-position bias table ------------------------------
__global__ void bias_table_kernel(const float* __restrict__ rel_bias,
                                  float* __restrict__ tab)
{
    int r = blockIdx.x * blockDim.x + threadIdx.x;
    if (r >= 2*SS - 1) return;
    int rel = r - (SS - 1);
    int n = -rel;
    int ret = (n < 0) ? 16 : 0;
    int na = n < 0 ? -n : n;
    int bucket;
    if (na < 8) {
        bucket = ret + na;
    } else {
        double v = log((double)na / 8.0) / log(16.0) * 8.0;
        int vi = 8 + (int)v;
        if (vi > 15) vi = 15;
        bucket = ret + vi;
    }
    #pragma unroll
    for (int h = 0; h < HH; h++) tab[r*HH + h] = rel_bias[bucket*HH + h];
}

// ---------------- fp32 -> fp16 hi/lo split -----------------------------------
__global__ __launch_bounds__(256)
void split_kernel(const float4* __restrict__ in, __half* __restrict__ oh,
                  __half* __restrict__ ol, int n4)
{
    int i = blockIdx.x * 256 + threadIdx.x;
    if (i >= n4) return;
    float4 v = in[i];
    __half2 l0, l1;
    __half2 h0 = split_h2(v.x, v.y, &l0);
    __half2 h1 = split_h2(v.z, v.w, &l1);
    __half2* po = (__half2*)(oh + (size_t)i*4);
    __half2* pl = (__half2*)(ol + (size_t)i*4);
    po[0] = h0; po[1] = h1;
    pl[0] = l0; pl[1] = l1;
}

// ---------------- fused transpose+split of all 6 weights ---------------------
struct TransArgs {
    const float* src[6];
    __half* dh[6];
    __half* dl[6];
    int K[6], N[6], base[6];
};
__global__ __launch_bounds__(256)
void transpose_all(TransArgs a)
{
    __shared__ float t[32][33];
    int bt = blockIdx.x;
    int reg = (bt < 1024) ? 0 : (bt < 2048) ? 1 : (bt < 3072) ? 2 :
              (bt < 4096) ? 3 : (bt < 8192) ? 4 : 5;
    int local = bt - a.base[reg];
    int K = a.K[reg], N = a.N[reg];
    int ntiles = N >> 5;
    int n0 = (local % ntiles) * 32, k0 = (local / ntiles) * 32;

    const float* in = a.src[reg];
    __half* oh = a.dh[reg];
    __half* ol = a.dl[reg];

    int tx = threadIdx.x, ty = threadIdx.y;
    #pragma unroll
    for (int i = 0; i < 32; i += 8)
        t[ty+i][tx] = in[(size_t)(k0+ty+i)*N + n0+tx];
    __syncthreads();
    #pragma unroll
    for (int i = 0; i < 32; i += 8){
        float v = t[tx][ty+i];
        __half h = __float2half_rn(v);
        oh[(size_t)(n0+ty+i)*K + k0+tx] = h;
        ol[(size_t)(n0+ty+i)*K + k0+tx] = __float2half_rn(v - __half2float(h));
    }
}

// ---------------- fused QKV GEMM (fp16 3-term) -------------------------------
// 256 threads, CTA 128x64, warp tile 32x32 (4x2 warps), BK=64, 2-stage.
// Stage: Ah 16K | Al 16K | Bh 8K | Bl 8K = 48K; 2 CTAs/SM -> 16 warps.
struct QKVArgs {
    const __half* Bh[3]; const __half* Bl[3];
    const float*  bias[3];
    __half* Oh[3]; __half* Ol[3];
};
#define GSM3 (2*49152)
__global__ __launch_bounds__(256, 2)
void qkv_gemm(const __half* __restrict__ Ah, const __half* __restrict__ Al,
              QKVArgs args, int M, int K)
{
    extern __shared__ __align__(1024) char smraw[];
    uint32_t sb = s2u(smraw);
    const int tid = threadIdx.x, wid = tid >> 5, lane = tid & 31;
    const int reg = blockIdx.x >> 4;
    const int n0 = (blockIdx.x & 15) * 64;
    const int m0 = blockIdx.y * 128;
    const int wm = (wid >> 1) * 32;     // 4 row groups of 32
    const int wn = (wid & 1) * 32;      // 2 col groups of 32
    const int N = DD;

    const int KT = K >> 6;
    const __half* pAh = Ah + (size_t)m0*K;
    const __half* pAl = Al + (size_t)m0*K;
    const __half* pBh = args.Bh[reg] + (size_t)n0*K;
    const __half* pBl = args.Bl[reg] + (size_t)n0*K;

    const uint32_t oAh = 0, oAl = 16384, oBh = 32768, oBl = 40960;
    const int arow = tid >> 3, acol = tid & 7;   // 32 rows/pass

    {
        #pragma unroll
        for (int i = 0; i < 4; i++){
            int r = arow + 32*i;
            cp16(sb + oAh + SWZ(r*128 + acol*16), pAh + (size_t)r*K + acol*8);
            cp16(sb + oAl + SWZ(r*128 + acol*16), pAl + (size_t)r*K + acol*8);
        }
        #pragma unroll
        for (int i = 0; i < 2; i++){
            int r = arow + 32*i;
            cp16(sb + oBh + SWZ(r*128 + acol*16), pBh + (size_t)r*K + acol*8);
            cp16(sb + oBl + SWZ(r*128 + acol*16), pBl + (size_t)r*K + acol*8);
        }
        asm volatile("cp.async.commit_group;" ::: "memory");
    }

    float acc[2][4][4];
    #pragma unroll
    for (int a = 0; a < 2; a++)
        #pragma unroll
        for (int b = 0; b < 4; b++)
            #pragma unroll
            for (int c = 0; c < 4; c++) acc[a][b][c] = 0.f;

    const int lrow = (lane & 7) + ((lane >> 3) & 1) * 8;
    const int koff = ((lane >> 4) & 1) * 16;

    for (int kt = 0; kt < KT; kt++){
        asm volatile("cp.async.wait_group 0;" ::: "memory");
        __syncthreads();

        uint32_t bufs = sb + (kt & 1) * 49152;

        if (kt + 1 < KT){
            uint32_t nbb = sb + ((kt + 1) & 1) * 49152;
            int k0 = (kt + 1) << 6;
            #pragma unroll
            for (int i = 0; i < 4; i++){
                int r = arow + 32*i;
                cp16(nbb + oAh + SWZ(r*128 + acol*16), pAh + (size_t)r*K + k0 + acol*8);
                cp16(nbb + oAl + SWZ(r*128 + acol*16), pAl + (size_t)r*K + k0 + acol*8);
            }
            #pragma unroll
            for (int i = 0; i < 2; i++){
                int r = arow + 32*i;
                cp16(nbb + oBh + SWZ(r*128 + acol*16), pBh + (size_t)r*K + k0 + acol*8);
                cp16(nbb + oBl + SWZ(r*128 + acol*16), pBl + (size_t)r*K + k0 + acol*8);
            }
            asm volatile("cp.async.commit_group;" ::: "memory");
        }

        #pragma unroll
        for (int ks = 0; ks < 4; ks++){
            const int kb = ks*32 + koff;
            uint32_t ah[2][4], al[2][4];
            #pragma unroll
            for (int mb = 0; mb < 2; mb++){
                int r = wm + mb*16 + lrow;
                ldm4(ah[mb], bufs + oAh + SWZ(r*128 + kb));
                ldm4(al[mb], bufs + oAl + SWZ(r*128 + kb));
            }
            #pragma unroll
            for (int nb = 0; nb < 2; nb++){
                uint32_t bh4[4], bl4[4];
                int r = wn + nb*16 + lrow;
                ldm4(bh4, bufs + oBh + SWZ(r*128 + kb));
                ldm4(bl4, bufs + oBl + SWZ(r*128 + kb));
                #pragma unroll
                for (int mb = 0; mb < 2; mb++)
                    mma_hf(acc[mb][2*nb+0], ah[mb], bh4[0], bh4[2]);
                #pragma unroll
                for (int mb = 0; mb < 2; mb++)
                    mma_hf(acc[mb][2*nb+1], ah[mb], bh4[1], bh4[3]);
                #pragma unroll
                for (int mb = 0; mb < 2; mb++)
                    mma_hf(acc[mb][2*nb+0], al[mb], bh4[0], bh4[2]);
                #pragma unroll
                for (int mb = 0; mb < 2; mb++)
                    mma_hf(acc[mb][2*nb+1], al[mb], bh4[1], bh4[3]);
                #pragma unroll
                for (int mb = 0; mb < 2; mb++)
                    mma_hf(acc[mb][2*nb+0], ah[mb], bl4[0], bl4[2]);
                #pragma unroll
                for (int mb = 0; mb < 2; mb++)
                    mma_hf(acc[mb][2*nb+1], ah[mb], bl4[1], bl4[3]);
            }
        }
    }

    const float* bias = args.bias[reg];
    __half* Oh = args.Oh[reg];
    __half* Ol = args.Ol[reg];
    const int erow = lane >> 2, ecol = (lane & 3) * 2;
    #pragma unroll
    for (int mb = 0; mb < 2; mb++){
        #pragma unroll
        for (int nf = 0; nf < 4; nf++){
            int r = m0 + wm + mb*16 + erow;
            int cc = n0 + wn + nf*8 + ecol;
            float b0 = bias[cc], b1 = bias[cc+1];
            float2 v0 = make_float2(acc[mb][nf][0] + b0, acc[mb][nf][1] + b1);
            float2 v1 = make_float2(acc[mb][nf][2] + b0, acc[mb][nf][3] + b1);
            if (reg < 2){
                __half2 l0, l1;
                __half2 h0 = split_h2(v0.x, v0.y, &l0);
                __half2 h1 = split_h2(v1.x, v1.y, &l1);
                *(__half2*)(Oh + (size_t)r*N + cc)     = h0;
                *(__half2*)(Ol + (size_t)r*N + cc)     = l0;
                *(__half2*)(Oh + (size_t)(r+8)*N + cc) = h1;
                *(__half2*)(Ol + (size_t)(r+8)*N + cc) = l1;
            } else {
                *(__half2*)(Oh + (size_t)r*N + cc) =
                    __halves2half2(__float2half_rn(v0.x), __float2half_rn(v0.y));
                *(__half2*)(Oh + (size_t)(r+8)*N + cc) =
                    __halves2half2(__float2half_rn(v1.x), __float2half_rn(v1.y));
            }
        }
    }
}

// ---------------- 2-term GEMM: A single fp16, B hi/lo ------------------------
// 256 threads, CTA 128x128, warp tile 32x64 (4x2 warps), BK=64, 2-stage.
// Stage: A 16K | Bh 16K | Bl 16K = 48K; 2 CTAs/SM -> 16 warps.
#define GSM2 (2*49152)
__global__ __launch_bounds__(256, 2)
void tcgemm2(const __half* __restrict__ A,
             const __half* __restrict__ Bh, const __half* __restrict__ Bl,
             const float* __restrict__ bias, float* __restrict__ C,
             __half* __restrict__ O16, int M, int N, int K, int relu)
{
    extern __shared__ __align__(1024) char smraw[];
    uint32_t sb = s2u(smraw);
    const int tid = threadIdx.x, wid = tid >> 5, lane = tid & 31;
    const int m0 = blockIdx.y*128, n0 = blockIdx.x*128;
    const int wm = (wid >> 1) * 32;     // 4 row groups of 32
    const int wn = (wid & 1) * 64;      // 2 col groups of 64

    const int KT = K >> 6;
    const __half* pA  = A  + (size_t)m0*K;
    const __half* pBh = Bh + (size_t)n0*K;
    const __half* pBl = Bl + (size_t)n0*K;

    const uint32_t oA = 0, oBh = 16384, oBl = 32768;
    const int arow = tid >> 3, acol = tid & 7;

    {
        #pragma unroll
        for (int i = 0; i < 4; i++){
            int r = arow + 32*i;
            cp16(sb + oA  + SWZ(r*128 + acol*16), pA  + (size_t)r*K + acol*8);
            cp16(sb + oBh + SWZ(r*128 + acol*16), pBh + (size_t)r*K + acol*8);
            cp16(sb + oBl + SWZ(r*128 + acol*16), pBl + (size_t)r*K + acol*8);
        }
        asm volatile("cp.async.commit_group;" ::: "memory");
    }

    float acc[2][8][4];
    #pragma unroll
    for (int a = 0; a < 2; a++)
        #pragma unroll
        for (int b = 0; b < 8; b++)
            #pragma unroll
            for (int c = 0; c < 4; c++) acc[a][b][c] = 0.f;

    const int lrow = (lane & 7) + ((lane >> 3) & 1) * 8;
    const int koff = ((lane >> 4) & 1) * 16;

    for (int kt = 0; kt < KT; kt++){
        asm volatile("cp.async.wait_group 0;" ::: "memory");
        __syncthreads();

        uint32_t bufs = sb + (kt & 1) * 49152;

        if (kt + 1 < KT){
            uint32_t nbb = sb + ((kt + 1) & 1) * 49152;
            int k0 = (kt + 1) << 6;
            #pragma unroll
            for (int i = 0; i < 4; i++){
                int r = arow + 32*i;
                cp16(nbb + oA  + SWZ(r*128 + acol*16), pA  + (size_t)r*K + k0 + acol*8);
                cp16(nbb + oBh + SWZ(r*128 + acol*16), pBh + (size_t)r*K + k0 + acol*8);
                cp16(nbb + oBl + SWZ(r*128 + acol*16), pBl + (size_t)r*K + k0 + acol*8);
            }
            asm volatile("cp.async.commit_group;" ::: "memory");
        }

        #pragma unroll
        for (int ks = 0; ks < 4; ks++){
            const int kb = ks*32 + koff;
            uint32_t ah[2][4];
            #pragma unroll
            for (int mb = 0; mb < 2; mb++){
                int r = wm + mb*16 + lrow;
                ldm4(ah[mb], bufs + oA + SWZ(r*128 + kb));
            }
            #pragma unroll
            for (int nb = 0; nb < 4; nb++){
                uint32_t bh4[4], bl4[4];
                int r = wn + nb*16 + lrow;
                ldm4(bh4, bufs + oBh + SWZ(r*128 + kb));
                ldm4(bl4, bufs + oBl + SWZ(r*128 + kb));
                #pragma unroll
                for (int mb = 0; mb < 2; mb++)
                    mma_hf(acc[mb][2*nb+0], ah[mb], bh4[0], bh4[2]);
                #pragma unroll
                for (int mb = 0; mb < 2; mb++)
                    mma_hf(acc[mb][2*nb+1], ah[mb], bh4[1], bh4[3]);
                #pragma unroll
                for (int mb = 0; mb < 2; mb++)
                    mma_hf(acc[mb][2*nb+0], ah[mb], bl4[0], bl4[2]);
                #pragma unroll
                for (int mb = 0; mb < 2; mb++)
                    mma_hf(acc[mb][2*nb+1], ah[mb], bl4[1], bl4[3]);
            }
        }
    }

    const int erow = lane >> 2, ecol = (lane & 3) * 2;
    #pragma unroll
    for (int mb = 0; mb < 2; mb++){
        #pragma unroll
        for (int nf = 0; nf < 8; nf++){
            int r = m0 + wm + mb*16 + erow;
            int cc = n0 + wn + nf*8 + ecol;
            float b0 = bias[cc], b1 = bias[cc+1];
            float2 v0 = make_float2(acc[mb][nf][0] + b0, acc[mb][nf][1] + b1);
            float2 v1 = make_float2(acc[mb][nf][2] + b0, acc[mb][nf][3] + b1);
            if (relu){
                v0.x = fmaxf(v0.x, 0.f); v0.y = fmaxf(v0.y, 0.f);
                v1.x = fmaxf(v1.x, 0.f); v1.y = fmaxf(v1.y, 0.f);
            }
            if (C){
                *(float2*)(C + (size_t)r*N + cc)     = v0;
                *(float2*)(C + (size_t)(r+8)*N + cc) = v1;
            }
            if (O16){
                *(__half2*)(O16 + (size_t)r*N + cc) =
                    __halves2half2(__float2half_rn(v0.x), __float2half_rn(v0.y));
                *(__half2*)(O16 + (size_t)(r+8)*N + cc) =
                    __halves2half2(__float2half_rn(v1.x), __float2half_rn(v1.y));
            }
        }
    }
}

// ---------------- tensor-core flash attention (fp16) -------------------------
#define AT_SMEM 83968
__global__ __launch_bounds__(256, 1)
void attn_tc(const __half* __restrict__ Qh_, const __half* __restrict__ Ql_,
             const __half* __restrict__ Kh_, const __half* __restrict__ Kl_,
             const __half* __restrict__ V_,
             const int* __restrict__ mask, const float* __restrict__ btab,
             __half* __restrict__ O16)
{
    extern __shared__ __align__(1024) char smraw[];
    uint32_t sb = s2u(smraw);
    const int tid = threadIdx.x, wid = tid >> 5, lane = tid & 31;
    const int g = blockIdx.y, q0 = blockIdx.x * 128;
    const int hh_ = g & (HH-1), bb = g >> 4;
    const int wq = wid * 16;
    const int lr = lane >> 2, lq = lane & 3;
    const int lrow = (lane & 7) + ((lane >> 3) & 1) * 8;
    const int koff = ((lane >> 4) & 1) * 16;

    const uint32_t oQh = 0, oQl = 16384, oKV = 32768;
    float* sbias = (float*)(smraw + 81920);
    float* spen  = (float*)(smraw + 82816);

    const size_t gb = (size_t)g * SS * DHD;

    {
        const __half* qh = Qh_ + gb + (size_t)q0 * DHD;
        const __half* ql = Ql_ + gb + (size_t)q0 * DHD;
        #pragma unroll
        for (int i = 0; i < 4; i++){
            int c = tid + 256*i, row = c >> 3, col = c & 7;
            cp16(sb + oQh + SWZ(row*128 + col*16), qh + (size_t)row*64 + col*8);
            cp16(sb + oQl + SWZ(row*128 + col*16), ql + (size_t)row*64 + col*8);
        }
    }
    {
        uint32_t kvb = sb + oKV;
        const __half* srcs[3] = { Kh_ + gb, Kl_ + gb, V_ + gb };
        #pragma unroll
        for (int t = 0; t < 3; t++)
            #pragma unroll
            for (int i = 0; i < 2; i++){
                int c = tid + 256*i, row = c >> 3, col = c & 7;
                cp16(kvb + t*8192 + SWZ(row*128 + col*16), srcs[t] + (size_t)row*64 + col*8);
            }
    }
    asm volatile("cp.async.commit_group;" ::: "memory");

    float m0v = -1e30f, m1v = -1e30f, l0 = 0.f, l1 = 0.f;
    float o[8][4];
    #pragma unroll
    for (int i = 0; i < 8; i++)
        #pragma unroll
        for (int j = 0; j < 4; j++) o[i][j] = 0.f;

    for (int ch = 0; ch < 16; ch++){
        const int k0 = ch * 64;
        if (tid < 192){
            int idx = tid + q0 - k0 - 63 + (SS - 1);
            if (idx < 0) idx = 0;
            if (idx > 2*SS - 2) idx = 2*SS - 2;
            sbias[tid] = btab[idx*HH + hh_];
        }
        if (tid < 64) spen[tid] = (mask[bb*SS + k0 + tid] == 0) ? -1e30f : 0.f;

        if (ch + 1 < 16){
            uint32_t kvb = sb + oKV + ((ch+1)&1)*24576;
            const size_t off = gb + (size_t)(k0 + 64)*64;
            const __half* srcs[3] = { Kh_+off, Kl_+off, V_+off };
            #pragma unroll
            for (int t = 0; t < 3; t++)
                #pragma unroll
                for (int i = 0; i < 2; i++){
                    int c = tid + 256*i, row = c >> 3, col = c & 7;
                    cp16(kvb + t*8192 + SWZ(row*128 + col*16), srcs[t] + (size_t)row*64 + col*8);
                }
            asm volatile("cp.async.commit_group;" ::: "memory");
            asm volatile("cp.async.wait_group 1;" ::: "memory");
        } else {
            asm volatile("cp.async.wait_group 0;" ::: "memory");
        }
        __syncthreads();

        const uint32_t kvb = sb + oKV + (ch&1)*24576;

        float s_[8][4];
        #pragma unroll
        for (int i = 0; i < 8; i++)
            #pragma unroll
            for (int j = 0; j < 4; j++) s_[i][j] = 0.f;

        #pragma unroll
        for (int kb = 0; kb < 4; kb++){
            uint32_t qa[4], qb[4];
            ldm4(qa, sb + oQh + SWZ((wq+lrow)*128 + kb*32 + koff));
            ldm4(qb, sb + oQl + SWZ((wq+lrow)*128 + kb*32 + koff));
            #pragma unroll
            for (int jp = 0; jp < 2; jp++){
                int j0 = 2*jp, j1 = 2*jp + 1;
                uint32_t kh0[4], kl0[4], kh1[4], kl1[4];
                ldm4(kh0, kvb +        SWZ((j0*16+lrow)*128 + kb*32 + koff));
                ldm4(kl0, kvb + 8192 + SWZ((j0*16+lrow)*128 + kb*32 + koff));
                ldm4(kh1, kvb +        SWZ((j1*16+lrow)*128 + kb*32 + koff));
                ldm4(kl1, kvb + 8192 + SWZ((j1*16+lrow)*128 + kb*32 + koff));
                mma_hf(s_[2*j0],   qa, kh0[0], kh0[2]);
                mma_hf(s_[2*j1],   qa, kh1[0], kh1[2]);
                mma_hf(s_[2*j0+1], qa, kh0[1], kh0[3]);
                mma_hf(s_[2*j1+1], qa, kh1[1], kh1[3]);
                mma_hf(s_[2*j0],   qb, kh0[0], kh0[2]);
                mma_hf(s_[2*j1],   qb, kh1[0], kh1[2]);
                mma_hf(s_[2*j0+1], qb, kh0[1], kh0[3]);
                mma_hf(s_[2*j1+1], qb, kh1[1], kh1[3]);
                mma_hf(s_[2*j0],   qa, kl0[0], kl0[2]);
                mma_hf(s_[2*j1],   qa, kl1[0], kl1[2]);
                mma_hf(s_[2*j0+1], qa, kl0[1], kl0[3]);
                mma_hf(s_[2*j1+1], qa, kl1[1], kl1[3]);
            }
        }

        const int r0 = wq + lr, r1 = r0 + 8;
        #pragma unroll
        for (int nf = 0; nf < 8; nf++){
            int c0 = nf*8 + lq*2;
            s_[nf][0] += sbias[r0 - c0 + 63] + spen[c0];
            s_[nf][1] += sbias[r0 - c0 + 62] + spen[c0+1];
            s_[nf][2] += sbias[r1 - c0 + 63] + spen[c0];
            s_[nf][3] += sbias[r1 - c0 + 62] + spen[c0+1];
        }

        float mx0 = -1e30f, mx1 = -1e30f;
        #pragma unroll
        for (int nf = 0; nf < 8; nf++){
            mx0 = fmaxf(mx0, fmaxf(s_[nf][0], s_[nf][1]));
            mx1 = fmaxf(mx1, fmaxf(s_[nf][2], s_[nf][3]));
        }
        #pragma unroll
        for (int off = 1; off < 4; off <<= 1){
            mx0 = fmaxf(mx0, __shfl_xor_sync(0xffffffffu, mx0, off));
            mx1 = fmaxf(mx1, __shfl_xor_sync(0xffffffffu, mx1, off));
        }
        float mn0 = fmaxf(m0v, mx0), mn1 = fmaxf(m1v, mx1);
        float al0 = __expf(m0v - mn0), al1 = __expf(m1v - mn1);
        float sum0 = 0.f, sum1 = 0.f;
        #pragma unroll
        for (int nf = 0; nf < 8; nf++){
            s_[nf][0] = __expf(s_[nf][0] - mn0); sum0 += s_[nf][0];
            s_[nf][1] = __expf(s_[nf][1] - mn0); sum0 += s_[nf][1];
            s_[nf][2] = __expf(s_[nf][2] - mn1); sum1 += s_[nf][2];
            s_[nf][3] = __expf(s_[nf][3] - mn1); sum1 += s_[nf][3];
        }
        #pragma unroll
        for (int off = 1; off < 4; off <<= 1){
            sum0 += __shfl_xor_sync(0xffffffffu, sum0, off);
            sum1 += __shfl_xor_sync(0xffffffffu, sum1, off);
        }
        l0 = l0*al0 + sum0; l1 = l1*al1 + sum1;
        m0v = mn0; m1v = mn1;
        #pragma unroll
        for (int nf = 0; nf < 8; nf++){
            o[nf][0] *= al0; o[nf][1] *= al0;
            o[nf][2] *= al1; o[nf][3] *= al1;
        }

        #pragma unroll
        for (int kb = 0; kb < 4; kb++){
            uint32_t ph[4], pl[4];
            {
                __half2 t0l, t1l, t2l, t3l;
                __half2 t0 = split_h2(s_[2*kb][0],   s_[2*kb][1],   &t0l);
                __half2 t1 = split_h2(s_[2*kb][2],   s_[2*kb][3],   &t1l);
                __half2 t2 = split_h2(s_[2*kb+1][0], s_[2*kb+1][1], &t2l);
                __half2 t3 = split_h2(s_[2*kb+1][2], s_[2*kb+1][3], &t3l);
                ph[0] = h2u(t0);  ph[1] = h2u(t1);  ph[2] = h2u(t2);  ph[3] = h2u(t3);
                pl[0] = h2u(t0l); pl[1] = h2u(t1l); pl[2] = h2u(t2l); pl[3] = h2u(t3l);
            }
            #pragma unroll
            for (int jp = 0; jp < 2; jp++){
                int j0 = 2*jp, j1 = 2*jp + 1;
                uint32_t v0[4], v1[4];
                ldm4t(v0, kvb + 16384 + SWZ((kb*16+lrow)*128 + j0*32 + koff));
                ldm4t(v1, kvb + 16384 + SWZ((kb*16+lrow)*128 + j1*32 + koff));
                mma_hf(o[2*j0],   ph, v0[0], v0[1]);
                mma_hf(o[2*j1],   ph, v1[0], v1[1]);
                mma_hf(o[2*j0+1], ph, v0[2], v0[3]);
                mma_hf(o[2*j1+1], ph, v1[2], v1[3]);
                mma_hf(o[2*j0],   pl, v0[0], v0[1]);
                mma_hf(o[2*j1],   pl, v1[0], v1[1]);
                mma_hf(o[2*j0+1], pl, v0[2], v0[3]);
                mma_hf(o[2*j1+1], pl, v1[2], v1[3]);
            }
        }
        __syncthreads();
    }

    const float inv0 = 1.f / l0, inv1 = 1.f / l1;
    const int tq0 = q0 + wq + lr, tq1 = tq0 + 8;
    const size_t b0 = (size_t)g*65536 + (size_t)tq0*64;
    const size_t b1 = (size_t)g*65536 + (size_t)tq1*64;
    #pragma unroll
    for (int nf = 0; nf < 8; nf++){
        int d0 = nf*8 + lq*2;
        *(__half2*)(O16 + b0 + d0) = __halves2half2(
            __float2half_rn(o[nf][0]*inv0), __float2half_rn(o[nf][1]*inv0));
        *(__half2*)(O16 + b1 + d0) = __halves2half2(
            __float2half_rn(o[nf][2]*inv1), __float2half_rn(o[nf][3]*inv1));
    }
}

// ---------------- LayerNorm with residual (register-resident) ----------------
__global__ __launch_bounds__(256)
void ln_kernel(const float4* __restrict__ A, const float4* __restrict__ R,
               const float4* __restrict__ gamma, const float4* __restrict__ beta,
               float4* __restrict__ Out, __half* __restrict__ O16)
{
    __shared__ float red[8];
    const int row = blockIdx.x, tid = threadIdx.x;
    const size_t base = (size_t)row * (DD/4);

    float4 a = A[base + tid], r4 = R[base + tid];
    float x0 = a.x + r4.x, x1 = a.y + r4.y, x2 = a.z + r4.z, x3 = a.w + r4.w;

    float lsum = x0 + x1 + x2 + x3;
    #pragma unroll
    for (int off = 16; off; off >>= 1) lsum += __shfl_xor_sync(0xffffffffu, lsum, off);
    if ((tid & 31) == 0) red[tid >> 5] = lsum;
    __syncthreads();
    float tot = 0.f;
    #pragma unroll
    for (int w = 0; w < 8; w++) tot += red[w];
    float mu = tot * (1.f / DD);
    __syncthreads();

    float d0 = x0-mu, d1 = x1-mu, d2 = x2-mu, d3 = x3-mu;
    float lsq = d0*d0 + d1*d1 + d2*d2 + d3*d3;
    #pragma unroll
    for (int off = 16; off; off >>= 1) lsq += __shfl_xor_sync(0xffffffffu, lsq, off);
    if ((tid & 31) == 0) red[tid >> 5] = lsq;
    __syncthreads();
    float vt = 0.f;
    #pragma unroll
    for (int w = 0; w < 8; w++) vt += red[w];
    float inv = rsqrtf(vt * (1.f / DD) + 1e-5f);

    float4 g = gamma[tid], b = beta[tid];
    float4 v;
    v.x = g.x * d0 * inv + b.x;
    v.y = g.y * d1 * inv + b.y;
    v.z = g.z * d2 * inv + b.z;
    v.w = g.w * d3 * inv + b.w;
    Out[base + tid] = v;
    if (O16){
        __half2* ph = (__half2*)(O16 + (size_t)row*DD + tid*4);
        ph[0] = __halves2half2(__float2half_rn(v.x), __float2half_rn(v.y));
        ph[1] = __halves2half2(__float2half_rn(v.z), __float2half_rn(v.w));
    }
}

// ---------------- launch ----------------------------------------------------
extern "C" void kernel_launch(void* const* d_in, const int* in_sizes, int n_in,
                              void* d_out, int out_size)
{
    const float* x    = (const float*)d_in[0];
    const int*   mask = (const int*)  d_in[1];
    const float* Wq = (const float*)d_in[2];  const float* bq = (const float*)d_in[3];
    const float* Wk = (const float*)d_in[4];  const float* bk = (const float*)d_in[5];
    const float* Wv = (const float*)d_in[6];  const float* bv = (const float*)d_in[7];
    const float* Wo = (const float*)d_in[8];  const float* bo = (const float*)d_in[9];
    const float* rel_bias = (const float*)d_in[10];
    const float* ln1g = (const float*)d_in[11]; const float* ln1b = (const float*)d_in[12];
    const float* W1 = (const float*)d_in[13]; const float* b1 = (const float*)d_in[14];
    const float* W2 = (const float*)d_in[15]; const float* b2 = (const float*)d_in[16];
    const float* ln2g = (const float*)d_in[17]; const float* ln2b = (const float*)d_in[18];
    float* out = (float*)d_out;

    float *tmp, *h, *btab;
    cudaGetSymbolAddress((void**)&tmp,  g_tmp);
    cudaGetSymbolAddress((void**)&h,    g_h);
    cudaGetSymbolAddress((void**)&btab, g_btab);

    __half *xh,*xl, *qh,*ql, *kh,*kl, *v16, *att16, *h16, *f16;
    __half *wqh,*wql,*wkh,*wkl,*wvh,*wvl,*woh,*wol,*w1h,*w1l,*w2h,*w2l;
    cudaGetSymbolAddress((void**)&xh,   g_xh);   cudaGetSymbolAddress((void**)&xl,   g_xl);
    cudaGetSymbolAddress((void**)&qh,   g_qh);   cudaGetSymbolAddress((void**)&ql,   g_ql);
    cudaGetSymbolAddress((void**)&kh,   g_kh);   cudaGetSymbolAddress((void**)&kl,   g_kl);
    cudaGetSymbolAddress((void**)&v16,  g_v16);
    cudaGetSymbolAddress((void**)&att16,g_att16);
    cudaGetSymbolAddress((void**)&h16,  g_h16);
    cudaGetSymbolAddress((void**)&f16,  g_f16);
    cudaGetSymbolAddress((void**)&wqh,  g_wqh);  cudaGetSymbolAddress((void**)&wql,  g_wql);
    cudaGetSymbolAddress((void**)&wkh,  g_wkh);  cudaGetSymbolAddress((void**)&wkl,  g_wkl);
    cudaGetSymbolAddress((void**)&wvh,  g_wvh);  cudaGetSymbolAddress((void**)&wvl,  g_wvl);
    cudaGetSymbolAddress((void**)&woh,  g_woh);  cudaGetSymbolAddress((void**)&wol,  g_wol);
    cudaGetSymbolAddress((void**)&w1h,  g_w1h);  cudaGetSymbolAddress((void**)&w1l,  g_w1l);
    cudaGetSymbolAddress((void**)&w2h,  g_w2h);  cudaGetSymbolAddress((void**)&w2l,  g_w2l);

    cudaFuncSetAttribute(qkv_gemm, cudaFuncAttributeMaxDynamicSharedMemorySize, GSM3);
    cudaFuncSetAttribute(tcgemm2,  cudaFuncAttributeMaxDynamicSharedMemorySize, GSM2);
    cudaFuncSetAttribute(attn_tc,  cudaFuncAttributeMaxDynamicSharedMemorySize, AT_SMEM);

    bias_table_kernel<<<(2*SS - 1 + 255)/256, 256>>>(rel_bias, btab);
    split_kernel<<<(MR*DD/4 + 255)/256, 256>>>((const float4*)x, xh, xl, MR*DD/4);
    {
        TransArgs ta;
        const float* srcs[6] = {Wq, Wk, Wv, Wo, W1, W2};
        __half* dh[6] = {wqh, wkh, wvh, woh, w1h, w2h};
        __half* dl[6] = {wql, wkl, wvl, wol, w1l, w2l};
        int Ks[6] = {DD, DD, DD, DD, DD, FF};
        int Ns[6] = {DD, DD, DD, DD, FF, DD};
        int bases[6] = {0, 1024, 2048, 3072, 4096, 8192};
        for (int i = 0; i < 6; i++){
            ta.src[i] = srcs[i]; ta.dh[i] = dh[i]; ta.dl[i] = dl[i];
            ta.K[i] = Ks[i]; ta.N[i] = Ns[i]; ta.base[i] = bases[i];
        }
        transpose_all<<<12288, dim3(32, 8)>>>(ta);
    }
    {
        QKVArgs qa;
        qa.Bh[0] = wqh; qa.Bl[0] = wql; qa.bias[0] = bq; qa.Oh[0] = qh;  qa.Ol[0] = ql;
        qa.Bh[1] = wkh; qa.Bl[1] = wkl; qa.bias[1] = bk; qa.Oh[1] = kh;  qa.Ol[1] = kl;
        qa.Bh[2] = wvh; qa.Bl[2] = wvl; qa.bias[2] = bv; qa.Oh[2] = v16; qa.Ol[2] = nullptr;
        qkv_gemm<<<dim3(48, MR/128), 256, GSM3>>>(xh, xl, qa, MR, DD);
    }
    attn_tc<<<dim3(SS/128, NG), 256, AT_SMEM>>>(qh, ql, kh, kl, v16,
                                                mask, btab, att16);
    tcgemm2<<<dim3(DD/128, MR/128), 256, GSM2>>>(att16, woh, wol, bo, tmp,
                                                 nullptr, MR, DD, DD, 0);
    ln_kernel<<<MR, 256>>>((const float4*)tmp, (const float4*)x,
                           (const float4*)ln1g, (const float4*)ln1b,
                           (float4*)h, h16);
    tcgemm2<<<dim3(FF/128, MR/128), 256, GSM2>>>(h16, w1h, w1l, b1, nullptr,
                                                 f16, MR, FF, DD, 1);
    tcgemm2<<<dim3(DD/128, MR/128), 256, GSM2>>>(f16, w2h, w2l, b2, tmp,
                                                 nullptr, MR, DD, FF, 0);
    ln_kernel<<<MR, 256>>>((const float4*)tmp, (const float4*)h,
                           (const float4*)ln2g, (const float4*)ln2b,
                           (float4*)out, nullptr);
}

// round 16
// speedup vs baseline: 1.1427x; 1.1427x over previous
#include <cuda_runtime.h>
#include <cuda_fp16.h>
#include <math.h>
#include <stdint.h>

#define BB 4
#define SS 1024
#define DD 1024
#define HH 16
#define FF 4096
#define DHD 64
#define NG (BB*HH)
#define MR (BB*SS)

// ---------------- scratch (static device globals; no allocation) -------------
__device__ float g_tmp[MR*DD];
__device__ float g_h[MR*DD];
__device__ float g_btab[(2*SS-1)*HH];

__device__ __half g_xh[MR*DD],  g_xl[MR*DD];   // xl kept for split kernel ABI; unused by QKV
__device__ __half g_qh[MR*DD],  g_ql[MR*DD];
__device__ __half g_kh[MR*DD],  g_kl[MR*DD];
__device__ __half g_v16[MR*DD];
__device__ __half g_att16[MR*DD];
__device__ __half g_h16[MR*DD];
__device__ __half g_f16[(size_t)MR*FF];
__device__ __half g_wqh[DD*DD], g_wql[DD*DD];
__device__ __half g_wkh[DD*DD], g_wkl[DD*DD];
__device__ __half g_wvh[DD*DD], g_wvl[DD*DD];
__device__ __half g_woh[DD*DD], g_wol[DD*DD];
__device__ __half g_w1h[(size_t)DD*FF], g_w1l[(size_t)DD*FF];
__device__ __half g_w2h[(size_t)FF*DD], g_w2l[(size_t)FF*DD];

// ---------------- PTX helpers ------------------------------------------------
#define SWZ(o) ((o) ^ (((o) >> 3) & 0x70))

__device__ __forceinline__ uint32_t s2u(const void* p){
    uint32_t a;
    asm("{ .reg .u64 t; cvta.to.shared.u64 t, %1; cvt.u32.u64 %0, t; }"
        : "=r"(a) : "l"(p));
    return a;
}
__device__ __forceinline__ void cp16(uint32_t d, const void* s){
    asm volatile("cp.async.cg.shared.global [%0], [%1], 16;" :: "r"(d), "l"(s));
}
__device__ __forceinline__ void ldm4(uint32_t* r, uint32_t a){
    asm volatile("ldmatrix.sync.aligned.m8n8.x4.shared.b16 {%0,%1,%2,%3}, [%4];"
        : "=r"(r[0]), "=r"(r[1]), "=r"(r[2]), "=r"(r[3]) : "r"(a));
}
__device__ __forceinline__ void ldm4t(uint32_t* r, uint32_t a){
    asm volatile("ldmatrix.sync.aligned.m8n8.x4.trans.shared.b16 {%0,%1,%2,%3}, [%4];"
        : "=r"(r[0]), "=r"(r[1]), "=r"(r[2]), "=r"(r[3]) : "r"(a));
}
__device__ __forceinline__ void mma_hf(float* c, const uint32_t* a,
                                       uint32_t b0, uint32_t b1){
    asm volatile("mma.sync.aligned.m16n8k16.row.col.f32.f16.f16.f32 "
        "{%0,%1,%2,%3}, {%4,%5,%6,%7}, {%8,%9}, {%0,%1,%2,%3};"
        : "+f"(c[0]), "+f"(c[1]), "+f"(c[2]), "+f"(c[3])
        : "r"(a[0]), "r"(a[1]), "r"(a[2]), "r"(a[3]), "r"(b0), "r"(b1));
}
__device__ __forceinline__ uint32_t h2u(__half2 v){ return *(uint32_t*)&v; }

__device__ __forceinline__ __half2 split_h2(float a, float b, __half2* lo){
    __half h0 = __float2half_rn(a), h1 = __float2half_rn(b);
    *lo = __halves2half2(__float2half_rn(a - __half2float(h0)),
                         __float2half_rn(b - __half2float(h1)));
    return __halves2half2(h0, h1);
}

// ---------------- relative-position bias table ------------------------------
__global__ void bias_table_kernel(const float* __restrict__ rel_bias,
                                  float* __restrict__ tab)
{
    int r = blockIdx.x * blockDim.x + threadIdx.x;
    if (r >= 2*SS - 1) return;
    int rel = r - (SS - 1);
    int n = -rel;
    int ret = (n < 0) ? 16 : 0;
    int na = n < 0 ? -n : n;
    int bucket;
    if (na < 8) {
        bucket = ret + na;
    } else {
        double v = log((double)na / 8.0) / log(16.0) * 8.0;
        int vi = 8 + (int)v;
        if (vi > 15) vi = 15;
        bucket = ret + vi;
    }
    #pragma unroll
    for (int h = 0; h < HH; h++) tab[r*HH + h] = rel_bias[bucket*HH + h];
}

// ---------------- fp32 -> fp16 single conversion -----------------------------
__global__ __launch_bounds__(256)
void tohalf_kernel(const float4* __restrict__ in, __half* __restrict__ oh, int n4)
{
    int i = blockIdx.x * 256 + threadIdx.x;
    if (i >= n4) return;
    float4 v = in[i];
    __half2* po = (__half2*)(oh + (size_t)i*4);
    po[0] = __halves2half2(__float2half_rn(v.x), __float2half_rn(v.y));
    po[1] = __halves2half2(__float2half_rn(v.z), __float2half_rn(v.w));
}

// ---------------- fused transpose+split of all 6 weights ---------------------
struct TransArgs {
    const float* src[6];
    __half* dh[6];
    __half* dl[6];
    int K[6], N[6], base[6];
};
__global__ __launch_bounds__(256)
void transpose_all(TransArgs a)
{
    __shared__ float t[32][33];
    int bt = blockIdx.x;
    int reg = (bt < 1024) ? 0 : (bt < 2048) ? 1 : (bt < 3072) ? 2 :
              (bt < 4096) ? 3 : (bt < 8192) ? 4 : 5;
    int local = bt - a.base[reg];
    int K = a.K[reg], N = a.N[reg];
    int ntiles = N >> 5;
    int n0 = (local % ntiles) * 32, k0 = (local / ntiles) * 32;

    const float* in = a.src[reg];
    __half* oh = a.dh[reg];
    __half* ol = a.dl[reg];

    int tx = threadIdx.x, ty = threadIdx.y;
    #pragma unroll
    for (int i = 0; i < 32; i += 8)
        t[ty+i][tx] = in[(size_t)(k0+ty+i)*N + n0+tx];
    __syncthreads();
    #pragma unroll
    for (int i = 0; i < 32; i += 8){
        float v = t[tx][ty+i];
        __half h = __float2half_rn(v);
        oh[(size_t)(n0+ty+i)*K + k0+tx] = h;
        ol[(size_t)(n0+ty+i)*K + k0+tx] = __float2half_rn(v - __half2float(h));
    }
}

// ---------------- fused QKV GEMM (2-term: A single, B hi/lo) ----------------
// 128 threads, CTA 128x128, warp tile 64x64 (2x2 warps), BK=64, 2-stage.
// Stage: A 16K | Bh 16K | Bl 16K = 48K; 2 CTAs/SM.
// Regions: 0=Q (hi/lo out), 1=K (hi/lo out), 2=V (single out).
struct QKVArgs {
    const __half* Bh[3]; const __half* Bl[3];
    const float*  bias[3];
    __half* Oh[3]; __half* Ol[3];
};
#define GSM3 (2*49152)
__global__ __launch_bounds__(128, 2)
void qkv_gemm(const __half* __restrict__ A, QKVArgs args, int M, int K)
{
    extern __shared__ __align__(1024) char smraw[];
    uint32_t sb = s2u(smraw);
    const int tid = threadIdx.x, wid = tid >> 5, lane = tid & 31;
    const int reg = blockIdx.x >> 3;
    const int n0 = (blockIdx.x & 7) * 128;
    const int m0 = blockIdx.y * 128;
    const int wm = (wid >> 1) * 64;
    const int wn = (wid & 1) * 64;
    const int N = DD;

    const int KT = K >> 6;
    const __half* pA  = A + (size_t)m0*K;
    const __half* pBh = args.Bh[reg] + (size_t)n0*K;
    const __half* pBl = args.Bl[reg] + (size_t)n0*K;

    const uint32_t oA = 0, oBh = 16384, oBl = 32768;
    const int arow = tid >> 3, acol = tid & 7;

    {
        #pragma unroll
        for (int i = 0; i < 8; i++){
            int r = arow + 16*i;
            cp16(sb + oA  + SWZ(r*128 + acol*16), pA  + (size_t)r*K + acol*8);
            cp16(sb + oBh + SWZ(r*128 + acol*16), pBh + (size_t)r*K + acol*8);
            cp16(sb + oBl + SWZ(r*128 + acol*16), pBl + (size_t)r*K + acol*8);
        }
        asm volatile("cp.async.commit_group;" ::: "memory");
    }

    float acc[4][8][4];
    #pragma unroll
    for (int a = 0; a < 4; a++)
        #pragma unroll
        for (int b = 0; b < 8; b++)
            #pragma unroll
            for (int c = 0; c < 4; c++) acc[a][b][c] = 0.f;

    const int lrow = (lane & 7) + ((lane >> 3) & 1) * 8;
    const int koff = ((lane >> 4) & 1) * 16;

    for (int kt = 0; kt < KT; kt++){
        asm volatile("cp.async.wait_group 0;" ::: "memory");
        __syncthreads();

        uint32_t bufs = sb + (kt & 1) * 49152;

        if (kt + 1 < KT){
            uint32_t nbb = sb + ((kt + 1) & 1) * 49152;
            int k0 = (kt + 1) << 6;
            #pragma unroll
            for (int i = 0; i < 8; i++){
                int r = arow + 16*i;
                cp16(nbb + oA  + SWZ(r*128 + acol*16), pA  + (size_t)r*K + k0 + acol*8);
                cp16(nbb + oBh + SWZ(r*128 + acol*16), pBh + (size_t)r*K + k0 + acol*8);
                cp16(nbb + oBl + SWZ(r*128 + acol*16), pBl + (size_t)r*K + k0 + acol*8);
            }
            asm volatile("cp.async.commit_group;" ::: "memory");
        }

        #pragma unroll
        for (int ks = 0; ks < 4; ks++){
            const int kb = ks*32 + koff;
            uint32_t ah[4][4];
            #pragma unroll
            for (int mb = 0; mb < 4; mb++){
                int r = wm + mb*16 + lrow;
                ldm4(ah[mb], bufs + oA + SWZ(r*128 + kb));
            }
            #pragma unroll
            for (int nb = 0; nb < 4; nb++){
                uint32_t bh4[4], bl4[4];
                int r = wn + nb*16 + lrow;
                ldm4(bh4, bufs + oBh + SWZ(r*128 + kb));
                ldm4(bl4, bufs + oBl + SWZ(r*128 + kb));
                #pragma unroll
                for (int mb = 0; mb < 4; mb++)
                    mma_hf(acc[mb][2*nb+0], ah[mb], bh4[0], bh4[2]);
                #pragma unroll
                for (int mb = 0; mb < 4; mb++)
                    mma_hf(acc[mb][2*nb+1], ah[mb], bh4[1], bh4[3]);
                #pragma unroll
                for (int mb = 0; mb < 4; mb++)
                    mma_hf(acc[mb][2*nb+0], ah[mb], bl4[0], bl4[2]);
                #pragma unroll
                for (int mb = 0; mb < 4; mb++)
                    mma_hf(acc[mb][2*nb+1], ah[mb], bl4[1], bl4[3]);
            }
        }
    }

    const float* bias = args.bias[reg];
    __half* Oh = args.Oh[reg];
    __half* Ol = args.Ol[reg];
    const int erow = lane >> 2, ecol = (lane & 3) * 2;
    #pragma unroll
    for (int mb = 0; mb < 4; mb++){
        #pragma unroll
        for (int nf = 0; nf < 8; nf++){
            int r = m0 + wm + mb*16 + erow;
            int cc = n0 + wn + nf*8 + ecol;
            float b0 = bias[cc], b1 = bias[cc+1];
            float2 v0 = make_float2(acc[mb][nf][0] + b0, acc[mb][nf][1] + b1);
            float2 v1 = make_float2(acc[mb][nf][2] + b0, acc[mb][nf][3] + b1);
            if (reg < 2){
                __half2 l0, l1;
                __half2 h0 = split_h2(v0.x, v0.y, &l0);
                __half2 h1 = split_h2(v1.x, v1.y, &l1);
                *(__half2*)(Oh + (size_t)r*N + cc)     = h0;
                *(__half2*)(Ol + (size_t)r*N + cc)     = l0;
                *(__half2*)(Oh + (size_t)(r+8)*N + cc) = h1;
                *(__half2*)(Ol + (size_t)(r+8)*N + cc) = l1;
            } else {
                *(__half2*)(Oh + (size_t)r*N + cc) =
                    __halves2half2(__float2half_rn(v0.x), __float2half_rn(v0.y));
                *(__half2*)(Oh + (size_t)(r+8)*N + cc) =
                    __halves2half2(__float2half_rn(v1.x), __float2half_rn(v1.y));
            }
        }
    }
}

// ---------------- 2-term GEMM: A single fp16, B hi/lo ------------------------
// 128 threads, CTA 128x128, warp tile 64x64 (2x2 warps), BK=64, 2-stage.
// Stage: A 16K | Bh 16K | Bl 16K = 48K; 2 CTAs/SM.  (round-10 shape, best)
#define GSM2 (2*49152)
__global__ __launch_bounds__(128, 2)
void tcgemm2(const __half* __restrict__ A,
             const __half* __restrict__ Bh, const __half* __restrict__ Bl,
             const float* __restrict__ bias, float* __restrict__ C,
             __half* __restrict__ O16, int M, int N, int K, int relu)
{
    extern __shared__ __align__(1024) char smraw[];
    uint32_t sb = s2u(smraw);
    const int tid = threadIdx.x, wid = tid >> 5, lane = tid & 31;
    const int m0 = blockIdx.y*128, n0 = blockIdx.x*128;
    const int wm = (wid >> 1) * 64;
    const int wn = (wid & 1) * 64;

    const int KT = K >> 6;
    const __half* pA  = A  + (size_t)m0*K;
    const __half* pBh = Bh + (size_t)n0*K;
    const __half* pBl = Bl + (size_t)n0*K;

    const uint32_t oA = 0, oBh = 16384, oBl = 32768;
    const int arow = tid >> 3, acol = tid & 7;

    {
        #pragma unroll
        for (int i = 0; i < 8; i++){
            int r = arow + 16*i;
            cp16(sb + oA  + SWZ(r*128 + acol*16), pA  + (size_t)r*K + acol*8);
            cp16(sb + oBh + SWZ(r*128 + acol*16), pBh + (size_t)r*K + acol*8);
            cp16(sb + oBl + SWZ(r*128 + acol*16), pBl + (size_t)r*K + acol*8);
        }
        asm volatile("cp.async.commit_group;" ::: "memory");
    }

    float acc[4][8][4];
    #pragma unroll
    for (int a = 0; a < 4; a++)
        #pragma unroll
        for (int b = 0; b < 8; b++)
            #pragma unroll
            for (int c = 0; c < 4; c++) acc[a][b][c] = 0.f;

    const int lrow = (lane & 7) + ((lane >> 3) & 1) * 8;
    const int koff = ((lane >> 4) & 1) * 16;

    for (int kt = 0; kt < KT; kt++){
        asm volatile("cp.async.wait_group 0;" ::: "memory");
        __syncthreads();

        uint32_t bufs = sb + (kt & 1) * 49152;

        if (kt + 1 < KT){
            uint32_t nbb = sb + ((kt + 1) & 1) * 49152;
            int k0 = (kt + 1) << 6;
            #pragma unroll
            for (int i = 0; i < 8; i++){
                int r = arow + 16*i;
                cp16(nbb + oA  + SWZ(r*128 + acol*16), pA  + (size_t)r*K + k0 + acol*8);
                cp16(nbb + oBh + SWZ(r*128 + acol*16), pBh + (size_t)r*K + k0 + acol*8);
                cp16(nbb + oBl + SWZ(r*128 + acol*16), pBl + (size_t)r*K + k0 + acol*8);
            }
            asm volatile("cp.async.commit_group;" ::: "memory");
        }

        #pragma unroll
        for (int ks = 0; ks < 4; ks++){
            const int kb = ks*32 + koff;
            uint32_t ah[4][4];
            #pragma unroll
            for (int mb = 0; mb < 4; mb++){
                int r = wm + mb*16 + lrow;
                ldm4(ah[mb], bufs + oA + SWZ(r*128 + kb));
            }
            #pragma unroll
            for (int nb = 0; nb < 4; nb++){
                uint32_t bh4[4], bl4[4];
                int r = wn + nb*16 + lrow;
                ldm4(bh4, bufs + oBh + SWZ(r*128 + kb));
                ldm4(bl4, bufs + oBl + SWZ(r*128 + kb));
                #pragma unroll
                for (int mb = 0; mb < 4; mb++)
                    mma_hf(acc[mb][2*nb+0], ah[mb], bh4[0], bh4[2]);
                #pragma unroll
                for (int mb = 0; mb < 4; mb++)
                    mma_hf(acc[mb][2*nb+1], ah[mb], bh4[1], bh4[3]);
                #pragma unroll
                for (int mb = 0; mb < 4; mb++)
                    mma_hf(acc[mb][2*nb+0], ah[mb], bl4[0], bl4[2]);
                #pragma unroll
                for (int mb = 0; mb < 4; mb++)
                    mma_hf(acc[mb][2*nb+1], ah[mb], bl4[1], bl4[3]);
            }
        }
    }

    const int erow = lane >> 2, ecol = (lane & 3) * 2;
    #pragma unroll
    for (int mb = 0; mb < 4; mb++){
        #pragma unroll
        for (int nf = 0; nf < 8; nf++){
            int r = m0 + wm + mb*16 + erow;
            int cc = n0 + wn + nf*8 + ecol;
            float b0 = bias[cc], b1 = bias[cc+1];
            float2 v0 = make_float2(acc[mb][nf][0] + b0, acc[mb][nf][1] + b1);
            float2 v1 = make_float2(acc[mb][nf][2] + b0, acc[mb][nf][3] + b1);
            if (relu){
                v0.x = fmaxf(v0.x, 0.f); v0.y = fmaxf(v0.y, 0.f);
                v1.x = fmaxf(v1.x, 0.f); v1.y = fmaxf(v1.y, 0.f);
            }
            if (C){
                *(float2*)(C + (size_t)r*N + cc)     = v0;
                *(float2*)(C + (size_t)(r+8)*N + cc) = v1;
            }
            if (O16){
                *(__half2*)(O16 + (size_t)r*N + cc) =
                    __halves2half2(__float2half_rn(v0.x), __float2half_rn(v0.y));
                *(__half2*)(O16 + (size_t)(r+8)*N + cc) =
                    __halves2half2(__float2half_rn(v1.x), __float2half_rn(v1.y));
            }
        }
    }
}

// ---------------- tensor-core flash attention (fp16) -------------------------
#define AT_SMEM 83968
__global__ __launch_bounds__(256, 1)
void attn_tc(const __half* __restrict__ Qh_, const __half* __restrict__ Ql_,
             const __half* __restrict__ Kh_, const __half* __restrict__ Kl_,
             const __half* __restrict__ V_,
             const int* __restrict__ mask, const float* __restrict__ btab,
             __half* __restrict__ O16)
{
    extern __shared__ __align__(1024) char smraw[];
    uint32_t sb = s2u(smraw);
    const int tid = threadIdx.x, wid = tid >> 5, lane = tid & 31;
    const int g = blockIdx.y, q0 = blockIdx.x * 128;
    const int hh_ = g & (HH-1), bb = g >> 4;
    const int wq = wid * 16;
    const int lr = lane >> 2, lq = lane & 3;
    const int lrow = (lane & 7) + ((lane >> 3) & 1) * 8;
    const int koff = ((lane >> 4) & 1) * 16;

    const uint32_t oQh = 0, oQl = 16384, oKV = 32768;
    float* sbias = (float*)(smraw + 81920);
    float* spen  = (float*)(smraw + 82816);

    const size_t gb = (size_t)g * SS * DHD;

    {
        const __half* qh = Qh_ + gb + (size_t)q0 * DHD;
        const __half* ql = Ql_ + gb + (size_t)q0 * DHD;
        #pragma unroll
        for (int i = 0; i < 4; i++){
            int c = tid + 256*i, row = c >> 3, col = c & 7;
            cp16(sb + oQh + SWZ(row*128 + col*16), qh + (size_t)row*64 + col*8);
            cp16(sb + oQl + SWZ(row*128 + col*16), ql + (size_t)row*64 + col*8);
        }
    }
    {
        uint32_t kvb = sb + oKV;
        const __half* srcs[3] = { Kh_ + gb, Kl_ + gb, V_ + gb };
        #pragma unroll
        for (int t = 0; t < 3; t++)
            #pragma unroll
            for (int i = 0; i < 2; i++){
                int c = tid + 256*i, row = c >> 3, col = c & 7;
                cp16(kvb + t*8192 + SWZ(row*128 + col*16), srcs[t] + (size_t)row*64 + col*8);
            }
    }
    asm volatile("cp.async.commit_group;" ::: "memory");

    float m0v = -1e30f, m1v = -1e30f, l0 = 0.f, l1 = 0.f;
    float o[8][4];
    #pragma unroll
    for (int i = 0; i < 8; i++)
        #pragma unroll
        for (int j = 0; j < 4; j++) o[i][j] = 0.f;

    for (int ch = 0; ch < 16; ch++){
        const int k0 = ch * 64;
        if (tid < 192){
            int idx = tid + q0 - k0 - 63 + (SS - 1);
            if (idx < 0) idx = 0;
            if (idx > 2*SS - 2) idx = 2*SS - 2;
            sbias[tid] = btab[idx*HH + hh_];
        }
        if (tid < 64) spen[tid] = (mask[bb*SS + k0 + tid] == 0) ? -1e30f : 0.f;

        if (ch + 1 < 16){
            uint32_t kvb = sb + oKV + ((ch+1)&1)*24576;
            const size_t off = gb + (size_t)(k0 + 64)*64;
            const __half* srcs[3] = { Kh_+off, Kl_+off, V_+off };
            #pragma unroll
            for (int t = 0; t < 3; t++)
                #pragma unroll
                for (int i = 0; i < 2; i++){
                    int c = tid + 256*i, row = c >> 3, col = c & 7;
                    cp16(kvb + t*8192 + SWZ(row*128 + col*16), srcs[t] + (size_t)row*64 + col*8);
                }
            asm volatile("cp.async.commit_group;" ::: "memory");
            asm volatile("cp.async.wait_group 1;" ::: "memory");
        } else {
            asm volatile("cp.async.wait_group 0;" ::: "memory");
        }
        __syncthreads();

        const uint32_t kvb = sb + oKV + (ch&1)*24576;

        float s_[8][4];
        #pragma unroll
        for (int i = 0; i < 8; i++)
            #pragma unroll
            for (int j = 0; j < 4; j++) s_[i][j] = 0.f;

        #pragma unroll
        for (int kb = 0; kb < 4; kb++){
            uint32_t qa[4], qb[4];
            ldm4(qa, sb + oQh + SWZ((wq+lrow)*128 + kb*32 + koff));
            ldm4(qb, sb + oQl + SWZ((wq+lrow)*128 + kb*32 + koff));
            #pragma unroll
            for (int jp = 0; jp < 2; jp++){
                int j0 = 2*jp, j1 = 2*jp + 1;
                uint32_t kh0[4], kl0[4], kh1[4], kl1[4];
                ldm4(kh0, kvb +        SWZ((j0*16+lrow)*128 + kb*32 + koff));
                ldm4(kl0, kvb + 8192 + SWZ((j0*16+lrow)*128 + kb*32 + koff));
                ldm4(kh1, kvb +        SWZ((j1*16+lrow)*128 + kb*32 + koff));
                ldm4(kl1, kvb + 8192 + SWZ((j1*16+lrow)*128 + kb*32 + koff));
                mma_hf(s_[2*j0],   qa, kh0[0], kh0[2]);
                mma_hf(s_[2*j1],   qa, kh1[0], kh1[2]);
                mma_hf(s_[2*j0+1], qa, kh0[1], kh0[3]);
                mma_hf(s_[2*j1+1], qa, kh1[1], kh1[3]);
                mma_hf(s_[2*j0],   qb, kh0[0], kh0[2]);
                mma_hf(s_[2*j1],   qb, kh1[0], kh1[2]);
                mma_hf(s_[2*j0+1], qb, kh0[1], kh0[3]);
                mma_hf(s_[2*j1+1], qb, kh1[1], kh1[3]);
                mma_hf(s_[2*j0],   qa, kl0[0], kl0[2]);
                mma_hf(s_[2*j1],   qa, kl1[0], kl1[2]);
                mma_hf(s_[2*j0+1], qa, kl0[1], kl0[3]);
                mma_hf(s_[2*j1+1], qa, kl1[1], kl1[3]);
            }
        }

        const int r0 = wq + lr, r1 = r0 + 8;
        #pragma unroll
        for (int nf = 0; nf < 8; nf++){
            int c0 = nf*8 + lq*2;
            s_[nf][0] += sbias[r0 - c0 + 63] + spen[c0];
            s_[nf][1] += sbias[r0 - c0 + 62] + spen[c0+1];
            s_[nf][2] += sbias[r1 - c0 + 63] + spen[c0];
            s_[nf][3] += sbias[r1 - c0 + 62] + spen[c0+1];
        }

        float mx0 = -1e30f, mx1 = -1e30f;
        #pragma unroll
        for (int nf = 0; nf < 8; nf++){
            mx0 = fmaxf(mx0, fmaxf(s_[nf][0], s_[nf][1]));
            mx1 = fmaxf(mx1, fmaxf(s_[nf][2], s_[nf][3]));
        }
        #pragma unroll
        for (int off = 1; off < 4; off <<= 1){
            mx0 = fmaxf(mx0, __shfl_xor_sync(0xffffffffu, mx0, off));
            mx1 = fmaxf(mx1, __shfl_xor_sync(0xffffffffu, mx1, off));
        }
        float mn0 = fmaxf(m0v, mx0), mn1 = fmaxf(m1v, mx1);
        float al0 = __expf(m0v - mn0), al1 = __expf(m1v - mn1);
        float sum0 = 0.f, sum1 = 0.f;
        #pragma unroll
        for (int nf = 0; nf < 8; nf++){
            s_[nf][0] = __expf(s_[nf][0] - mn0); sum0 += s_[nf][0];
            s_[nf][1] = __expf(s_[nf][1] - mn0); sum0 += s_[nf][1];
            s_[nf][2] = __expf(s_[nf][2] - mn1); sum1 += s_[nf][2];
            s_[nf][3] = __expf(s_[nf][3] - mn1); sum1 += s_[nf][3];
        }
        #pragma unroll
        for (int off = 1; off < 4; off <<= 1){
            sum0 += __shfl_xor_sync(0xffffffffu, sum0, off);
            sum1 += __shfl_xor_sync(0xffffffffu, sum1, off);
        }
        l0 = l0*al0 + sum0; l1 = l1*al1 + sum1;
        m0v = mn0; m1v = mn1;
        #pragma unroll
        for (int nf = 0; nf < 8; nf++){
            o[nf][0] *= al0; o[nf][1] *= al0;
            o[nf][2] *= al1; o[nf][3] *= al1;
        }

        #pragma unroll
        for (int kb = 0; kb < 4; kb++){
            uint32_t ph[4], pl[4];
            {
                __half2 t0l, t1l, t2l, t3l;
                __half2 t0 = split_h2(s_[2*kb][0],   s_[2*kb][1],   &t0l);
                __half2 t1 = split_h2(s_[2*kb][2],   s_[2*kb][3],   &t1l);
                __half2 t2 = split_h2(s_[2*kb+1][0], s_[2*kb+1][1], &t2l);
                __half2 t3 = split_h2(s_[2*kb+1][2], s_[2*kb+1][3], &t3l);
                ph[0] = h2u(t0);  ph[1] = h2u(t1);  ph[2] = h2u(t2);  ph[3] = h2u(t3);
                pl[0] = h2u(t0l); pl[1] = h2u(t1l); pl[2] = h2u(t2l); pl[3] = h2u(t3l);
            }
            #pragma unroll
            for (int jp = 0; jp < 2; jp++){
                int j0 = 2*jp, j1 = 2*jp + 1;
                uint32_t v0[4], v1[4];
                ldm4t(v0, kvb + 16384 + SWZ((kb*16+lrow)*128 + j0*32 + koff));
                ldm4t(v1, kvb + 16384 + SWZ((kb*16+lrow)*128 + j1*32 + koff));
                mma_hf(o[2*j0],   ph, v0[0], v0[1]);
                mma_hf(o[2*j1],   ph, v1[0], v1[1]);
                mma_hf(o[2*j0+1], ph, v0[2], v0[3]);
                mma_hf(o[2*j1+1], ph, v1[2], v1[3]);
                mma_hf(o[2*j0],   pl, v0[0], v0[1]);
                mma_hf(o[2*j1],   pl, v1[0], v1[1]);
                mma_hf(o[2*j0+1], pl, v0[2], v0[3]);
                mma_hf(o[2*j1+1], pl, v1[2], v1[3]);
            }
        }
        __syncthreads();
    }

    const float inv0 = 1.f / l0, inv1 = 1.f / l1;
    const int tq0 = q0 + wq + lr, tq1 = tq0 + 8;
    const size_t b0 = (size_t)g*65536 + (size_t)tq0*64;
    const size_t b1 = (size_t)g*65536 + (size_t)tq1*64;
    #pragma unroll
    for (int nf = 0; nf < 8; nf++){
        int d0 = nf*8 + lq*2;
        *(__half2*)(O16 + b0 + d0) = __halves2half2(
            __float2half_rn(o[nf][0]*inv0), __float2half_rn(o[nf][1]*inv0));
        *(__half2*)(O16 + b1 + d0) = __halves2half2(
            __float2half_rn(o[nf][2]*inv1), __float2half_rn(o[nf][3]*inv1));
    }
}

// ---------------- LayerNorm with residual (register-resident) ----------------
__global__ __launch_bounds__(256)
void ln_kernel(const float4* __restrict__ A, const float4* __restrict__ R,
               const float4* __restrict__ gamma, const float4* __restrict__ beta,
               float4* __restrict__ Out, __half* __restrict__ O16)
{
    __shared__ float red[8];
    const int row = blockIdx.x, tid = threadIdx.x;
    const size_t base = (size_t)row * (DD/4);

    float4 a = A[base + tid], r4 = R[base + tid];
    float x0 = a.x + r4.x, x1 = a.y + r4.y, x2 = a.z + r4.z, x3 = a.w + r4.w;

    float lsum = x0 + x1 + x2 + x3;
    #pragma unroll
    for (int off = 16; off; off >>= 1) lsum += __shfl_xor_sync(0xffffffffu, lsum, off);
    if ((tid & 31) == 0) red[tid >> 5] = lsum;
    __syncthreads();
    float tot = 0.f;
    #pragma unroll
    for (int w = 0; w < 8; w++) tot += red[w];
    float mu = tot * (1.f / DD);
    __syncthreads();

    float d0 = x0-mu, d1 = x1-mu, d2 = x2-mu, d3 = x3-mu;
    float lsq = d0*d0 + d1*d1 + d2*d2 + d3*d3;
    #pragma unroll
    for (int off = 16; off; off >>= 1) lsq += __shfl_xor_sync(0xffffffffu, lsq, off);
    if ((tid & 31) == 0) red[tid >> 5] = lsq;
    __syncthreads();
    float vt = 0.f;
    #pragma unroll
    for (int w = 0; w < 8; w++) vt += red[w];
    float inv = rsqrtf(vt * (1.f / DD) + 1e-5f);

    float4 g = gamma[tid], b = beta[tid];
    float4 v;
    v.x = g.x * d0 * inv + b.x;
    v.y = g.y * d1 * inv + b.y;
    v.z = g.z * d2 * inv + b.z;
    v.w = g.w * d3 * inv + b.w;
    Out[base + tid] = v;
    if (O16){
        __half2* ph = (__half2*)(O16 + (size_t)row*DD + tid*4);
        ph[0] = __halves2half2(__float2half_rn(v.x), __float2half_rn(v.y));
        ph[1] = __halves2half2(__float2half_rn(v.z), __float2half_rn(v.w));
    }
}

// ---------------- launch ----------------------------------------------------
extern "C" void kernel_launch(void* const* d_in, const int* in_sizes, int n_in,
                              void* d_out, int out_size)
{
    const float* x    = (const float*)d_in[0];
    const int*   mask = (const int*)  d_in[1];
    const float* Wq = (const float*)d_in[2];  const float* bq = (const float*)d_in[3];
    const float* Wk = (const float*)d_in[4];  const float* bk = (const float*)d_in[5];
    const float* Wv = (const float*)d_in[6];  const float* bv = (const float*)d_in[7];
    const float* Wo = (const float*)d_in[8];  const float* bo = (const float*)d_in[9];
    const float* rel_bias = (const float*)d_in[10];
    const float* ln1g = (const float*)d_in[11]; const float* ln1b = (const float*)d_in[12];
    const float* W1 = (const float*)d_in[13]; const float* b1 = (const float*)d_in[14];
    const float* W2 = (const float*)d_in[15]; const float* b2 = (const float*)d_in[16];
    const float* ln2g = (const float*)d_in[17]; const float* ln2b = (const float*)d_in[18];
    float* out = (float*)d_out;

    float *tmp, *h, *btab;
    cudaGetSymbolAddress((void**)&tmp,  g_tmp);
    cudaGetSymbolAddress((void**)&h,    g_h);
    cudaGetSymbolAddress((void**)&btab, g_btab);

    __half *xh, *qh,*ql, *kh,*kl, *v16, *att16, *h16, *f16;
    __half *wqh,*wql,*wkh,*wkl,*wvh,*wvl,*woh,*wol,*w1h,*w1l,*w2h,*w2l;
    cudaGetSymbolAddress((void**)&xh,   g_xh);
    cudaGetSymbolAddress((void**)&qh,   g_qh);   cudaGetSymbolAddress((void**)&ql,   g_ql);
    cudaGetSymbolAddress((void**)&kh,   g_kh);   cudaGetSymbolAddress((void**)&kl,   g_kl);
    cudaGetSymbolAddress((void**)&v16,  g_v16);
    cudaGetSymbolAddress((void**)&att16,g_att16);
    cudaGetSymbolAddress((void**)&h16,  g_h16);
    cudaGetSymbolAddress((void**)&f16,  g_f16);
    cudaGetSymbolAddress((void**)&wqh,  g_wqh);  cudaGetSymbolAddress((void**)&wql,  g_wql);
    cudaGetSymbolAddress((void**)&wkh,  g_wkh);  cudaGetSymbolAddress((void**)&wkl,  g_wkl);
    cudaGetSymbolAddress((void**)&wvh,  g_wvh);  cudaGetSymbolAddress((void**)&wvl,  g_wvl);
    cudaGetSymbolAddress((void**)&woh,  g_woh);  cudaGetSymbolAddress((void**)&wol,  g_wol);
    cudaGetSymbolAddress((void**)&w1h,  g_w1h);  cudaGetSymbolAddress((void**)&w1l,  g_w1l);
    cudaGetSymbolAddress((void**)&w2h,  g_w2h);  cudaGetSymbolAddress((void**)&w2l,  g_w2l);

    cudaFuncSetAttribute(qkv_gemm, cudaFuncAttributeMaxDynamicSharedMemorySize, GSM3);
    cudaFuncSetAttribute(tcgemm2,  cudaFuncAttributeMaxDynamicSharedMemorySize, GSM2);
    cudaFuncSetAttribute(attn_tc,  cudaFuncAttributeMaxDynamicSharedMemorySize, AT_SMEM);

    bias_table_kernel<<<(2*SS - 1 + 255)/256, 256>>>(rel_bias, btab);
    tohalf_kernel<<<(MR*DD/4 + 255)/256, 256>>>((const float4*)x, xh, MR*DD/4);
    {
        TransArgs ta;
        const float* srcs[6] = {Wq, Wk, Wv, Wo, W1, W2};
        __half* dh[6] = {wqh, wkh, wvh, woh, w1h, w2h};
        __half* dl[6] = {wql, wkl, wvl, wol, w1l, w2l};
        int Ks[6] = {DD, DD, DD, DD, DD, FF};
        int Ns[6] = {DD, DD, DD, DD, FF, DD};
        int bases[6] = {0, 1024, 2048, 3072, 4096, 8192};
        for (int i = 0; i < 6; i++){
            ta.src[i] = srcs[i]; ta.dh[i] = dh[i]; ta.dl[i] = dl[i];
            ta.K[i] = Ks[i]; ta.N[i] = Ns[i]; ta.base[i] = bases[i];
        }
        transpose_all<<<12288, dim3(32, 8)>>>(ta);
    }
    {
        QKVArgs qa;
        qa.Bh[0] = wqh; qa.Bl[0] = wql; qa.bias[0] = bq; qa.Oh[0] = qh;  qa.Ol[0] = ql;
        qa.Bh[1] = wkh; qa.Bl[1] = wkl; qa.bias[1] = bk; qa.Oh[1] = kh;  qa.Ol[1] = kl;
        qa.Bh[2] = wvh; qa.Bl[2] = wvl; qa.bias[2] = bv; qa.Oh[2] = v16; qa.Ol[2] = nullptr;
        qkv_gemm<<<dim3(24, MR/128), 128, GSM3>>>(xh, qa, MR, DD);
    }
    attn_tc<<<dim3(SS/128, NG), 256, AT_SMEM>>>(qh, ql, kh, kl, v16,
                                                mask, btab, att16);
    tcgemm2<<<dim3(DD/128, MR/128), 128, GSM2>>>(att16, woh, wol, bo, tmp,
                                                 nullptr, MR, DD, DD, 0);
    ln_kernel<<<MR, 256>>>((const float4*)tmp, (const float4*)x,
                           (const float4*)ln1g, (const float4*)ln1b,
                           (float4*)h, h16);
    tcgemm2<<<dim3(FF/128, MR/128), 128, GSM2>>>(h16, w1h, w1l, b1, nullptr,
                                                 f16, MR, FF, DD, 1);
    tcgemm2<<<dim3(DD/128, MR/128), 128, GSM2>>>(f16, w2h, w2l, b2, tmp,
                                                 nullptr, MR, DD, FF, 0);
    ln_kernel<<<MR, 256>>>((const float4*)tmp, (const float4*)h,
                           (const float4*)ln2g, (const float4*)ln2b,
                           (float4*)out, nullptr);
}

// round 17
// speedup vs baseline: 1.2035x; 1.0532x over previous
#include <cuda_runtime.h>
#include <cuda_fp16.h>
#include <math.h>
#include <stdint.h>

#define BB 4
#define SS 1024
#define DD 1024
#define HH 16
#define FF 4096
#define DHD 64
#define NG (BB*HH)
#define MR (BB*SS)

// ---------------- scratch (static device globals; no allocation) -------------
__device__ float g_tmp[MR*DD];
__device__ float g_h[MR*DD];
__device__ float g_btab[(2*SS-1)*HH];

__device__ __half g_xh[MR*DD];
__device__ __half g_q16[MR*DD];
__device__ __half g_kh[MR*DD],  g_kl[MR*DD];
__device__ __half g_v16[MR*DD];
__device__ __half g_att16[MR*DD];
__device__ __half g_h16[MR*DD];
__device__ __half g_f16[(size_t)MR*FF];
__device__ __half g_wqh[DD*DD], g_wql[DD*DD];
__device__ __half g_wkh[DD*DD], g_wkl[DD*DD];
__device__ __half g_wvh[DD*DD], g_wvl[DD*DD];
__device__ __half g_woh[DD*DD], g_wol[DD*DD];
__device__ __half g_w1h[(size_t)DD*FF], g_w1l[(size_t)DD*FF];
__device__ __half g_w2h[(size_t)FF*DD], g_w2l[(size_t)FF*DD];

// ---------------- PTX helpers ------------------------------------------------
#define SWZ(o) ((o) ^ (((o) >> 3) & 0x70))

__device__ __forceinline__ uint32_t s2u(const void* p){
    uint32_t a;
    asm("{ .reg .u64 t; cvta.to.shared.u64 t, %1; cvt.u32.u64 %0, t; }"
        : "=r"(a) : "l"(p));
    return a;
}
__device__ __forceinline__ void cp16(uint32_t d, const void* s){
    asm volatile("cp.async.cg.shared.global [%0], [%1], 16;" :: "r"(d), "l"(s));
}
__device__ __forceinline__ void ldm4(uint32_t* r, uint32_t a){
    asm volatile("ldmatrix.sync.aligned.m8n8.x4.shared.b16 {%0,%1,%2,%3}, [%4];"
        : "=r"(r[0]), "=r"(r[1]), "=r"(r[2]), "=r"(r[3]) : "r"(a));
}
__device__ __forceinline__ void ldm4t(uint32_t* r, uint32_t a){
    asm volatile("ldmatrix.sync.aligned.m8n8.x4.trans.shared.b16 {%0,%1,%2,%3}, [%4];"
        : "=r"(r[0]), "=r"(r[1]), "=r"(r[2]), "=r"(r[3]) : "r"(a));
}
__device__ __forceinline__ void mma_hf(float* c, const uint32_t* a,
                                       uint32_t b0, uint32_t b1){
    asm volatile("mma.sync.aligned.m16n8k16.row.col.f32.f16.f16.f32 "
        "{%0,%1,%2,%3}, {%4,%5,%6,%7}, {%8,%9}, {%0,%1,%2,%3};"
        : "+f"(c[0]), "+f"(c[1]), "+f"(c[2]), "+f"(c[3])
        : "r"(a[0]), "r"(a[1]), "r"(a[2]), "r"(a[3]), "r"(b0), "r"(b1));
}
__device__ __forceinline__ uint32_t h2u(__half2 v){ return *(uint32_t*)&v; }

__device__ __forceinline__ __half2 split_h2(float a, float b, __half2* lo){
    __half h0 = __float2half_rn(a), h1 = __float2half_rn(b);
    *lo = __halves2half2(__float2half_rn(a - __half2float(h0)),
                         __float2half_rn(b - __half2float(h1)));
    return __halves2half2(h0, h1);
}

// ---------------- relative-position bias table ------------------------------
__global__ void bias_table_kernel(const float* __restrict__ rel_bias,
                                  float* __restrict__ tab)
{
    int r = blockIdx.x * blockDim.x + threadIdx.x;
    if (r >= 2*SS - 1) return;
    int rel = r - (SS - 1);
    int n = -rel;
    int ret = (n < 0) ? 16 : 0;
    int na = n < 0 ? -n : n;
    int bucket;
    if (na < 8) {
        bucket = ret + na;
    } else {
        double v = log((double)na / 8.0) / log(16.0) * 8.0;
        int vi = 8 + (int)v;
        if (vi > 15) vi = 15;
        bucket = ret + vi;
    }
    #pragma unroll
    for (int h = 0; h < HH; h++) tab[r*HH + h] = rel_bias[bucket*HH + h];
}

// ---------------- fp32 -> fp16 single conversion -----------------------------
__global__ __launch_bounds__(256)
void tohalf_kernel(const float4* __restrict__ in, __half* __restrict__ oh, int n4)
{
    int i = blockIdx.x * 256 + threadIdx.x;
    if (i >= n4) return;
    float4 v = in[i];
    __half2* po = (__half2*)(oh + (size_t)i*4);
    po[0] = __halves2half2(__float2half_rn(v.x), __float2half_rn(v.y));
    po[1] = __halves2half2(__float2half_rn(v.z), __float2half_rn(v.w));
}

// ---------------- fused transpose+split of all 6 weights ---------------------
struct TransArgs {
    const float* src[6];
    __half* dh[6];
    __half* dl[6];
    int K[6], N[6], base[6];
};
__global__ __launch_bounds__(256)
void transpose_all(TransArgs a)
{
    __shared__ float t[32][33];
    int bt = blockIdx.x;
    int reg = (bt < 1024) ? 0 : (bt < 2048) ? 1 : (bt < 3072) ? 2 :
              (bt < 4096) ? 3 : (bt < 8192) ? 4 : 5;
    int local = bt - a.base[reg];
    int K = a.K[reg], N = a.N[reg];
    int ntiles = N >> 5;
    int n0 = (local % ntiles) * 32, k0 = (local / ntiles) * 32;

    const float* in = a.src[reg];
    __half* oh = a.dh[reg];
    __half* ol = a.dl[reg];

    int tx = threadIdx.x, ty = threadIdx.y;
    #pragma unroll
    for (int i = 0; i < 32; i += 8)
        t[ty+i][tx] = in[(size_t)(k0+ty+i)*N + n0+tx];
    __syncthreads();
    #pragma unroll
    for (int i = 0; i < 32; i += 8){
        float v = t[tx][ty+i];
        __half h = __float2half_rn(v);
        oh[(size_t)(n0+ty+i)*K + k0+tx] = h;
        ol[(size_t)(n0+ty+i)*K + k0+tx] = __float2half_rn(v - __half2float(h));
    }
}

// ---------------- fused QKV GEMM (2-term: A single, B hi/lo) ----------------
// 128 threads, CTA 128x128, warp tile 64x64 (2x2 warps), BK=64, 2-stage.
// Regions: 0=Q (single out), 1=K (hi/lo out), 2=V (single out).
struct QKVArgs {
    const __half* Bh[3]; const __half* Bl[3];
    const float*  bias[3];
    __half* Oh[3]; __half* Ol[3];
};
#define GSM3 (2*49152)
__global__ __launch_bounds__(128, 2)
void qkv_gemm(const __half* __restrict__ A, QKVArgs args, int M, int K)
{
    extern __shared__ __align__(1024) char smraw[];
    uint32_t sb = s2u(smraw);
    const int tid = threadIdx.x, wid = tid >> 5, lane = tid & 31;
    const int reg = blockIdx.x >> 3;
    const int n0 = (blockIdx.x & 7) * 128;
    const int m0 = blockIdx.y * 128;
    const int wm = (wid >> 1) * 64;
    const int wn = (wid & 1) * 64;
    const int N = DD;

    const int KT = K >> 6;
    const __half* pA  = A + (size_t)m0*K;
    const __half* pBh = args.Bh[reg] + (size_t)n0*K;
    const __half* pBl = args.Bl[reg] + (size_t)n0*K;

    const uint32_t oA = 0, oBh = 16384, oBl = 32768;
    const int arow = tid >> 3, acol = tid & 7;

    {
        #pragma unroll
        for (int i = 0; i < 8; i++){
            int r = arow + 16*i;
            cp16(sb + oA  + SWZ(r*128 + acol*16), pA  + (size_t)r*K + acol*8);
            cp16(sb + oBh + SWZ(r*128 + acol*16), pBh + (size_t)r*K + acol*8);
            cp16(sb + oBl + SWZ(r*128 + acol*16), pBl + (size_t)r*K + acol*8);
        }
        asm volatile("cp.async.commit_group;" ::: "memory");
    }

    float acc[4][8][4];
    #pragma unroll
    for (int a = 0; a < 4; a++)
        #pragma unroll
        for (int b = 0; b < 8; b++)
            #pragma unroll
            for (int c = 0; c < 4; c++) acc[a][b][c] = 0.f;

    const int lrow = (lane & 7) + ((lane >> 3) & 1) * 8;
    const int koff = ((lane >> 4) & 1) * 16;

    for (int kt = 0; kt < KT; kt++){
        asm volatile("cp.async.wait_group 0;" ::: "memory");
        __syncthreads();

        uint32_t bufs = sb + (kt & 1) * 49152;

        if (kt + 1 < KT){
            uint32_t nbb = sb + ((kt + 1) & 1) * 49152;
            int k0 = (kt + 1) << 6;
            #pragma unroll
            for (int i = 0; i < 8; i++){
                int r = arow + 16*i;
                cp16(nbb + oA  + SWZ(r*128 + acol*16), pA  + (size_t)r*K + k0 + acol*8);
                cp16(nbb + oBh + SWZ(r*128 + acol*16), pBh + (size_t)r*K + k0 + acol*8);
                cp16(nbb + oBl + SWZ(r*128 + acol*16), pBl + (size_t)r*K + k0 + acol*8);
            }
            asm volatile("cp.async.commit_group;" ::: "memory");
        }

        #pragma unroll
        for (int ks = 0; ks < 4; ks++){
            const int kb = ks*32 + koff;
            uint32_t ah[4][4];
            #pragma unroll
            for (int mb = 0; mb < 4; mb++){
                int r = wm + mb*16 + lrow;
                ldm4(ah[mb], bufs + oA + SWZ(r*128 + kb));
            }
            #pragma unroll
            for (int nb = 0; nb < 4; nb++){
                uint32_t bh4[4], bl4[4];
                int r = wn + nb*16 + lrow;
                ldm4(bh4, bufs + oBh + SWZ(r*128 + kb));
                ldm4(bl4, bufs + oBl + SWZ(r*128 + kb));
                #pragma unroll
                for (int mb = 0; mb < 4; mb++)
                    mma_hf(acc[mb][2*nb+0], ah[mb], bh4[0], bh4[2]);
                #pragma unroll
                for (int mb = 0; mb < 4; mb++)
                    mma_hf(acc[mb][2*nb+1], ah[mb], bh4[1], bh4[3]);
                #pragma unroll
                for (int mb = 0; mb < 4; mb++)
                    mma_hf(acc[mb][2*nb+0], ah[mb], bl4[0], bl4[2]);
                #pragma unroll
                for (int mb = 0; mb < 4; mb++)
                    mma_hf(acc[mb][2*nb+1], ah[mb], bl4[1], bl4[3]);
            }
        }
    }

    const float* bias = args.bias[reg];
    __half* Oh = args.Oh[reg];
    __half* Ol = args.Ol[reg];
    const int erow = lane >> 2, ecol = (lane & 3) * 2;
    #pragma unroll
    for (int mb = 0; mb < 4; mb++){
        #pragma unroll
        for (int nf = 0; nf < 8; nf++){
            int r = m0 + wm + mb*16 + erow;
            int cc = n0 + wn + nf*8 + ecol;
            float b0 = bias[cc], b1 = bias[cc+1];
            float2 v0 = make_float2(acc[mb][nf][0] + b0, acc[mb][nf][1] + b1);
            float2 v1 = make_float2(acc[mb][nf][2] + b0, acc[mb][nf][3] + b1);
            if (reg == 1){
                __half2 l0, l1;
                __half2 h0 = split_h2(v0.x, v0.y, &l0);
                __half2 h1 = split_h2(v1.x, v1.y, &l1);
                *(__half2*)(Oh + (size_t)r*N + cc)     = h0;
                *(__half2*)(Ol + (size_t)r*N + cc)     = l0;
                *(__half2*)(Oh + (size_t)(r+8)*N + cc) = h1;
                *(__half2*)(Ol + (size_t)(r+8)*N + cc) = l1;
            } else {
                *(__half2*)(Oh + (size_t)r*N + cc) =
                    __halves2half2(__float2half_rn(v0.x), __float2half_rn(v0.y));
                *(__half2*)(Oh + (size_t)(r+8)*N + cc) =
                    __halves2half2(__float2half_rn(v1.x), __float2half_rn(v1.y));
            }
        }
    }
}

// ---------------- 2-term GEMM: A single fp16, B hi/lo ------------------------
#define GSM2 (2*49152)
__global__ __launch_bounds__(128, 2)
void tcgemm2(const __half* __restrict__ A,
             const __half* __restrict__ Bh, const __half* __restrict__ Bl,
             const float* __restrict__ bias, float* __restrict__ C,
             __half* __restrict__ O16, int M, int N, int K, int relu)
{
    extern __shared__ __align__(1024) char smraw[];
    uint32_t sb = s2u(smraw);
    const int tid = threadIdx.x, wid = tid >> 5, lane = tid & 31;
    const int m0 = blockIdx.y*128, n0 = blockIdx.x*128;
    const int wm = (wid >> 1) * 64;
    const int wn = (wid & 1) * 64;

    const int KT = K >> 6;
    const __half* pA  = A  + (size_t)m0*K;
    const __half* pBh = Bh + (size_t)n0*K;
    const __half* pBl = Bl + (size_t)n0*K;

    const uint32_t oA = 0, oBh = 16384, oBl = 32768;
    const int arow = tid >> 3, acol = tid & 7;

    {
        #pragma unroll
        for (int i = 0; i < 8; i++){
            int r = arow + 16*i;
            cp16(sb + oA  + SWZ(r*128 + acol*16), pA  + (size_t)r*K + acol*8);
            cp16(sb + oBh + SWZ(r*128 + acol*16), pBh + (size_t)r*K + acol*8);
            cp16(sb + oBl + SWZ(r*128 + acol*16), pBl + (size_t)r*K + acol*8);
        }
        asm volatile("cp.async.commit_group;" ::: "memory");
    }

    float acc[4][8][4];
    #pragma unroll
    for (int a = 0; a < 4; a++)
        #pragma unroll
        for (int b = 0; b < 8; b++)
            #pragma unroll
            for (int c = 0; c < 4; c++) acc[a][b][c] = 0.f;

    const int lrow = (lane & 7) + ((lane >> 3) & 1) * 8;
    const int koff = ((lane >> 4) & 1) * 16;

    for (int kt = 0; kt < KT; kt++){
        asm volatile("cp.async.wait_group 0;" ::: "memory");
        __syncthreads();

        uint32_t bufs = sb + (kt & 1) * 49152;

        if (kt + 1 < KT){
            uint32_t nbb = sb + ((kt + 1) & 1) * 49152;
            int k0 = (kt + 1) << 6;
            #pragma unroll
            for (int i = 0; i < 8; i++){
                int r = arow + 16*i;
                cp16(nbb + oA  + SWZ(r*128 + acol*16), pA  + (size_t)r*K + k0 + acol*8);
                cp16(nbb + oBh + SWZ(r*128 + acol*16), pBh + (size_t)r*K + k0 + acol*8);
                cp16(nbb + oBl + SWZ(r*128 + acol*16), pBl + (size_t)r*K + k0 + acol*8);
            }
            asm volatile("cp.async.commit_group;" ::: "memory");
        }

        #pragma unroll
        for (int ks = 0; ks < 4; ks++){
            const int kb = ks*32 + koff;
            uint32_t ah[4][4];
            #pragma unroll
            for (int mb = 0; mb < 4; mb++){
                int r = wm + mb*16 + lrow;
                ldm4(ah[mb], bufs + oA + SWZ(r*128 + kb));
            }
            #pragma unroll
            for (int nb = 0; nb < 4; nb++){
                uint32_t bh4[4], bl4[4];
                int r = wn + nb*16 + lrow;
                ldm4(bh4, bufs + oBh + SWZ(r*128 + kb));
                ldm4(bl4, bufs + oBl + SWZ(r*128 + kb));
                #pragma unroll
                for (int mb = 0; mb < 4; mb++)
                    mma_hf(acc[mb][2*nb+0], ah[mb], bh4[0], bh4[2]);
                #pragma unroll
                for (int mb = 0; mb < 4; mb++)
                    mma_hf(acc[mb][2*nb+1], ah[mb], bh4[1], bh4[3]);
                #pragma unroll
                for (int mb = 0; mb < 4; mb++)
                    mma_hf(acc[mb][2*nb+0], ah[mb], bl4[0], bl4[2]);
                #pragma unroll
                for (int mb = 0; mb < 4; mb++)
                    mma_hf(acc[mb][2*nb+1], ah[mb], bl4[1], bl4[3]);
            }
        }
    }

    const int erow = lane >> 2, ecol = (lane & 3) * 2;
    #pragma unroll
    for (int mb = 0; mb < 4; mb++){
        #pragma unroll
        for (int nf = 0; nf < 8; nf++){
            int r = m0 + wm + mb*16 + erow;
            int cc = n0 + wn + nf*8 + ecol;
            float b0 = bias[cc], b1 = bias[cc+1];
            float2 v0 = make_float2(acc[mb][nf][0] + b0, acc[mb][nf][1] + b1);
            float2 v1 = make_float2(acc[mb][nf][2] + b0, acc[mb][nf][3] + b1);
            if (relu){
                v0.x = fmaxf(v0.x, 0.f); v0.y = fmaxf(v0.y, 0.f);
                v1.x = fmaxf(v1.x, 0.f); v1.y = fmaxf(v1.y, 0.f);
            }
            if (C){
                *(float2*)(C + (size_t)r*N + cc)     = v0;
                *(float2*)(C + (size_t)(r+8)*N + cc) = v1;
            }
            if (O16){
                *(__half2*)(O16 + (size_t)r*N + cc) =
                    __halves2half2(__float2half_rn(v0.x), __float2half_rn(v0.y));
                *(__half2*)(O16 + (size_t)(r+8)*N + cc) =
                    __halves2half2(__float2half_rn(v1.x), __float2half_rn(v1.y));
            }
        }
    }
}

// ---------------- tensor-core flash attention (fp16) -------------------------
// QK: 2-term (Q single; K hi/lo).  PV: 2-term (P hi/lo; V single).
// smem: Qh 16K | 2 x (Kh 8K | Kl 8K | V 8K) = 64K | bias 768B | pen 256B.
// 2 CTAs/SM via launch_bounds(256,2).
#define AT_SMEM 66560
__global__ __launch_bounds__(256, 2)
void attn_tc(const __half* __restrict__ Q_,
             const __half* __restrict__ Kh_, const __half* __restrict__ Kl_,
             const __half* __restrict__ V_,
             const int* __restrict__ mask, const float* __restrict__ btab,
             __half* __restrict__ O16)
{
    extern __shared__ __align__(1024) char smraw[];
    uint32_t sb = s2u(smraw);
    const int tid = threadIdx.x, wid = tid >> 5, lane = tid & 31;
    const int g = blockIdx.y, q0 = blockIdx.x * 128;
    const int hh_ = g & (HH-1), bb = g >> 4;
    const int wq = wid * 16;
    const int lr = lane >> 2, lq = lane & 3;
    const int lrow = (lane & 7) + ((lane >> 3) & 1) * 8;
    const int koff = ((lane >> 4) & 1) * 16;

    const uint32_t oQ = 0, oKV = 16384;       // KV buf stride 24576
    float* sbias = (float*)(smraw + 65536);   // 192 floats
    float* spen  = (float*)(smraw + 66304);   // 64 floats

    const size_t gb = (size_t)g * SS * DHD;

    {
        const __half* q = Q_ + gb + (size_t)q0 * DHD;
        #pragma unroll
        for (int i = 0; i < 4; i++){
            int c = tid + 256*i, row = c >> 3, col = c & 7;
            cp16(sb + oQ + SWZ(row*128 + col*16), q + (size_t)row*64 + col*8);
        }
    }
    {
        uint32_t kvb = sb + oKV;
        const __half* srcs[3] = { Kh_ + gb, Kl_ + gb, V_ + gb };
        #pragma unroll
        for (int t = 0; t < 3; t++)
            #pragma unroll
            for (int i = 0; i < 2; i++){
                int c = tid + 256*i, row = c >> 3, col = c & 7;
                cp16(kvb + t*8192 + SWZ(row*128 + col*16), srcs[t] + (size_t)row*64 + col*8);
            }
    }
    asm volatile("cp.async.commit_group;" ::: "memory");

    float m0v = -1e30f, m1v = -1e30f, l0 = 0.f, l1 = 0.f;
    float o[8][4];
    #pragma unroll
    for (int i = 0; i < 8; i++)
        #pragma unroll
        for (int j = 0; j < 4; j++) o[i][j] = 0.f;

    for (int ch = 0; ch < 16; ch++){
        const int k0 = ch * 64;
        if (tid < 192){
            int idx = tid + q0 - k0 - 63 + (SS - 1);
            if (idx < 0) idx = 0;
            if (idx > 2*SS - 2) idx = 2*SS - 2;
            sbias[tid] = btab[idx*HH + hh_];
        }
        if (tid < 64) spen[tid] = (mask[bb*SS + k0 + tid] == 0) ? -1e30f : 0.f;

        if (ch + 1 < 16){
            uint32_t kvb = sb + oKV + ((ch+1)&1)*24576;
            const size_t off = gb + (size_t)(k0 + 64)*64;
            const __half* srcs[3] = { Kh_+off, Kl_+off, V_+off };
            #pragma unroll
            for (int t = 0; t < 3; t++)
                #pragma unroll
                for (int i = 0; i < 2; i++){
                    int c = tid + 256*i, row = c >> 3, col = c & 7;
                    cp16(kvb + t*8192 + SWZ(row*128 + col*16), srcs[t] + (size_t)row*64 + col*8);
                }
            asm volatile("cp.async.commit_group;" ::: "memory");
            asm volatile("cp.async.wait_group 1;" ::: "memory");
        } else {
            asm volatile("cp.async.wait_group 0;" ::: "memory");
        }
        __syncthreads();

        const uint32_t kvb = sb + oKV + (ch&1)*24576;

        float s_[8][4];
        #pragma unroll
        for (int i = 0; i < 8; i++)
            #pragma unroll
            for (int j = 0; j < 4; j++) s_[i][j] = 0.f;

        #pragma unroll
        for (int kb = 0; kb < 4; kb++){
            uint32_t qa[4];
            ldm4(qa, sb + oQ + SWZ((wq+lrow)*128 + kb*32 + koff));
            #pragma unroll
            for (int jp = 0; jp < 2; jp++){
                int j0 = 2*jp, j1 = 2*jp + 1;
                uint32_t kh0[4], kl0[4], kh1[4], kl1[4];
                ldm4(kh0, kvb +        SWZ((j0*16+lrow)*128 + kb*32 + koff));
                ldm4(kl0, kvb + 8192 + SWZ((j0*16+lrow)*128 + kb*32 + koff));
                ldm4(kh1, kvb +        SWZ((j1*16+lrow)*128 + kb*32 + koff));
                ldm4(kl1, kvb + 8192 + SWZ((j1*16+lrow)*128 + kb*32 + koff));
                mma_hf(s_[2*j0],   qa, kh0[0], kh0[2]);
                mma_hf(s_[2*j1],   qa, kh1[0], kh1[2]);
                mma_hf(s_[2*j0+1], qa, kh0[1], kh0[3]);
                mma_hf(s_[2*j1+1], qa, kh1[1], kh1[3]);
                mma_hf(s_[2*j0],   qa, kl0[0], kl0[2]);
                mma_hf(s_[2*j1],   qa, kl1[0], kl1[2]);
                mma_hf(s_[2*j0+1], qa, kl0[1], kl0[3]);
                mma_hf(s_[2*j1+1], qa, kl1[1], kl1[3]);
            }
        }

        const int r0 = wq + lr, r1 = r0 + 8;
        #pragma unroll
        for (int nf = 0; nf < 8; nf++){
            int c0 = nf*8 + lq*2;
            s_[nf][0] += sbias[r0 - c0 + 63] + spen[c0];
            s_[nf][1] += sbias[r0 - c0 + 62] + spen[c0+1];
            s_[nf][2] += sbias[r1 - c0 + 63] + spen[c0];
            s_[nf][3] += sbias[r1 - c0 + 62] + spen[c0+1];
        }

        float mx0 = -1e30f, mx1 = -1e30f;
        #pragma unroll
        for (int nf = 0; nf < 8; nf++){
            mx0 = fmaxf(mx0, fmaxf(s_[nf][0], s_[nf][1]));
            mx1 = fmaxf(mx1, fmaxf(s_[nf][2], s_[nf][3]));
        }
        #pragma unroll
        for (int off = 1; off < 4; off <<= 1){
            mx0 = fmaxf(mx0, __shfl_xor_sync(0xffffffffu, mx0, off));
            mx1 = fmaxf(mx1, __shfl_xor_sync(0xffffffffu, mx1, off));
        }
        float mn0 = fmaxf(m0v, mx0), mn1 = fmaxf(m1v, mx1);
        float al0 = __expf(m0v - mn0), al1 = __expf(m1v - mn1);
        float sum0 = 0.f, sum1 = 0.f;
        #pragma unroll
        for (int nf = 0; nf < 8; nf++){
            s_[nf][0] = __expf(s_[nf][0] - mn0); sum0 += s_[nf][0];
            s_[nf][1] = __expf(s_[nf][1] - mn0); sum0 += s_[nf][1];
            s_[nf][2] = __expf(s_[nf][2] - mn1); sum1 += s_[nf][2];
            s_[nf][3] = __expf(s_[nf][3] - mn1); sum1 += s_[nf][3];
        }
        #pragma unroll
        for (int off = 1; off < 4; off <<= 1){
            sum0 += __shfl_xor_sync(0xffffffffu, sum0, off);
            sum1 += __shfl_xor_sync(0xffffffffu, sum1, off);
        }
        l0 = l0*al0 + sum0; l1 = l1*al1 + sum1;
        m0v = mn0; m1v = mn1;
        #pragma unroll
        for (int nf = 0; nf < 8; nf++){
            o[nf][0] *= al0; o[nf][1] *= al0;
            o[nf][2] *= al1; o[nf][3] *= al1;
        }

        #pragma unroll
        for (int kb = 0; kb < 4; kb++){
            uint32_t ph[4], pl[4];
            {
                __half2 t0l, t1l, t2l, t3l;
                __half2 t0 = split_h2(s_[2*kb][0],   s_[2*kb][1],   &t0l);
                __half2 t1 = split_h2(s_[2*kb][2],   s_[2*kb][3],   &t1l);
                __half2 t2 = split_h2(s_[2*kb+1][0], s_[2*kb+1][1], &t2l);
                __half2 t3 = split_h2(s_[2*kb+1][2], s_[2*kb+1][3], &t3l);
                ph[0] = h2u(t0);  ph[1] = h2u(t1);  ph[2] = h2u(t2);  ph[3] = h2u(t3);
                pl[0] = h2u(t0l); pl[1] = h2u(t1l); pl[2] = h2u(t2l); pl[3] = h2u(t3l);
            }
            #pragma unroll
            for (int jp = 0; jp < 2; jp++){
                int j0 = 2*jp, j1 = 2*jp + 1;
                uint32_t v0[4], v1[4];
                ldm4t(v0, kvb + 16384 + SWZ((kb*16+lrow)*128 + j0*32 + koff));
                ldm4t(v1, kvb + 16384 + SWZ((kb*16+lrow)*128 + j1*32 + koff));
                mma_hf(o[2*j0],   ph, v0[0], v0[1]);
                mma_hf(o[2*j1],   ph, v1[0], v1[1]);
                mma_hf(o[2*j0+1], ph, v0[2], v0[3]);
                mma_hf(o[2*j1+1], ph, v1[2], v1[3]);
                mma_hf(o[2*j0],   pl, v0[0], v0[1]);
                mma_hf(o[2*j1],   pl, v1[0], v1[1]);
                mma_hf(o[2*j0+1], pl, v0[2], v0[3]);
                mma_hf(o[2*j1+1], pl, v1[2], v1[3]);
            }
        }
        __syncthreads();
    }

    const float inv0 = 1.f / l0, inv1 = 1.f / l1;
    const int tq0 = q0 + wq + lr, tq1 = tq0 + 8;
    const size_t b0 = (size_t)g*65536 + (size_t)tq0*64;
    const size_t b1 = (size_t)g*65536 + (size_t)tq1*64;
    #pragma unroll
    for (int nf = 0; nf < 8; nf++){
        int d0 = nf*8 + lq*2;
        *(__half2*)(O16 + b0 + d0) = __halves2half2(
            __float2half_rn(o[nf][0]*inv0), __float2half_rn(o[nf][1]*inv0));
        *(__half2*)(O16 + b1 + d0) = __halves2half2(
            __float2half_rn(o[nf][2]*inv1), __float2half_rn(o[nf][3]*inv1));
    }
}

// ---------------- LayerNorm with residual (register-resident) ----------------
__global__ __launch_bounds__(256)
void ln_kernel(const float4* __restrict__ A, const float4* __restrict__ R,
               const float4* __restrict__ gamma, const float4* __restrict__ beta,
               float4* __restrict__ Out, __half* __restrict__ O16)
{
    __shared__ float red[8];
    const int row = blockIdx.x, tid = threadIdx.x;
    const size_t base = (size_t)row * (DD/4);

    float4 a = A[base + tid], r4 = R[base + tid];
    float x0 = a.x + r4.x, x1 = a.y + r4.y, x2 = a.z + r4.z, x3 = a.w + r4.w;

    float lsum = x0 + x1 + x2 + x3;
    #pragma unroll
    for (int off = 16; off; off >>= 1) lsum += __shfl_xor_sync(0xffffffffu, lsum, off);
    if ((tid & 31) == 0) red[tid >> 5] = lsum;
    __syncthreads();
    float tot = 0.f;
    #pragma unroll
    for (int w = 0; w < 8; w++) tot += red[w];
    float mu = tot * (1.f / DD);
    __syncthreads();

    float d0 = x0-mu, d1 = x1-mu, d2 = x2-mu, d3 = x3-mu;
    float lsq = d0*d0 + d1*d1 + d2*d2 + d3*d3;
    #pragma unroll
    for (int off = 16; off; off >>= 1) lsq += __shfl_xor_sync(0xffffffffu, lsq, off);
    if ((tid & 31) == 0) red[tid >> 5] = lsq;
    __syncthreads();
    float vt = 0.f;
    #pragma unroll
    for (int w = 0; w < 8; w++) vt += red[w];
    float inv = rsqrtf(vt * (1.f / DD) + 1e-5f);

    float4 g = gamma[tid], b = beta[tid];
    float4 v;
    v.x = g.x * d0 * inv + b.x;
    v.y = g.y * d1 * inv + b.y;
    v.z = g.z * d2 * inv + b.z;
    v.w = g.w * d3 * inv + b.w;
    Out[base + tid] = v;
    if (O16){
        __half2* ph = (__half2*)(O16 + (size_t)row*DD + tid*4);
        ph[0] = __halves2half2(__float2half_rn(v.x), __float2half_rn(v.y));
        ph[1] = __halves2half2(__float2half_rn(v.z), __float2half_rn(v.w));
    }
}

// ---------------- launch ----------------------------------------------------
extern "C" void kernel_launch(void* const* d_in, const int* in_sizes, int n_in,
                              void* d_out, int out_size)
{
    const float* x    = (const float*)d_in[0];
    const int*   mask = (const int*)  d_in[1];
    const float* Wq = (const float*)d_in[2];  const float* bq = (const float*)d_in[3];
    const float* Wk = (const float*)d_in[4];  const float* bk = (const float*)d_in[5];
    const float* Wv = (const float*)d_in[6];  const float* bv = (const float*)d_in[7];
    const float* Wo = (const float*)d_in[8];  const float* bo = (const float*)d_in[9];
    const float* rel_bias = (const float*)d_in[10];
    const float* ln1g = (const float*)d_in[11]; const float* ln1b = (const float*)d_in[12];
    const float* W1 = (const float*)d_in[13]; const float* b1 = (const float*)d_in[14];
    const float* W2 = (const float*)d_in[15]; const float* b2 = (const float*)d_in[16];
    const float* ln2g = (const float*)d_in[17]; const float* ln2b = (const float*)d_in[18];
    float* out = (float*)d_out;

    float *tmp, *h, *btab;
    cudaGetSymbolAddress((void**)&tmp,  g_tmp);
    cudaGetSymbolAddress((void**)&h,    g_h);
    cudaGetSymbolAddress((void**)&btab, g_btab);

    __half *xh, *q16, *kh,*kl, *v16, *att16, *h16, *f16;
    __half *wqh,*wql,*wkh,*wkl,*wvh,*wvl,*woh,*wol,*w1h,*w1l,*w2h,*w2l;
    cudaGetSymbolAddress((void**)&xh,   g_xh);
    cudaGetSymbolAddress((void**)&q16,  g_q16);
    cudaGetSymbolAddress((void**)&kh,   g_kh);   cudaGetSymbolAddress((void**)&kl,   g_kl);
    cudaGetSymbolAddress((void**)&v16,  g_v16);
    cudaGetSymbolAddress((void**)&att16,g_att16);
    cudaGetSymbolAddress((void**)&h16,  g_h16);
    cudaGetSymbolAddress((void**)&f16,  g_f16);
    cudaGetSymbolAddress((void**)&wqh,  g_wqh);  cudaGetSymbolAddress((void**)&wql,  g_wql);
    cudaGetSymbolAddress((void**)&wkh,  g_wkh);  cudaGetSymbolAddress((void**)&wkl,  g_wkl);
    cudaGetSymbolAddress((void**)&wvh,  g_wvh);  cudaGetSymbolAddress((void**)&wvl,  g_wvl);
    cudaGetSymbolAddress((void**)&woh,  g_woh);  cudaGetSymbolAddress((void**)&wol,  g_wol);
    cudaGetSymbolAddress((void**)&w1h,  g_w1h);  cudaGetSymbolAddress((void**)&w1l,  g_w1l);
    cudaGetSymbolAddress((void**)&w2h,  g_w2h);  cudaGetSymbolAddress((void**)&w2l,  g_w2l);

    cudaFuncSetAttribute(qkv_gemm, cudaFuncAttributeMaxDynamicSharedMemorySize, GSM3);
    cudaFuncSetAttribute(tcgemm2,  cudaFuncAttributeMaxDynamicSharedMemorySize, GSM2);
    cudaFuncSetAttribute(attn_tc,  cudaFuncAttributeMaxDynamicSharedMemorySize, AT_SMEM);

    bias_table_kernel<<<(2*SS - 1 + 255)/256, 256>>>(rel_bias, btab);
    tohalf_kernel<<<(MR*DD/4 + 255)/256, 256>>>((const float4*)x, xh, MR*DD/4);
    {
        TransArgs ta;
        const float* srcs[6] = {Wq, Wk, Wv, Wo, W1, W2};
        __half* dh[6] = {wqh, wkh, wvh, woh, w1h, w2h};
        __half* dl[6] = {wql, wkl, wvl, wol, w1l, w2l};
        int Ks[6] = {DD, DD, DD, DD, DD, FF};
        int Ns[6] = {DD, DD, DD, DD, FF, DD};
        int bases[6] = {0, 1024, 2048, 3072, 4096, 8192};
        for (int i = 0; i < 6; i++){
            ta.src[i] = srcs[i]; ta.dh[i] = dh[i]; ta.dl[i] = dl[i];
            ta.K[i] = Ks[i]; ta.N[i] = Ns[i]; ta.base[i] = bases[i];
        }
        transpose_all<<<12288, dim3(32, 8)>>>(ta);
    }
    {
        QKVArgs qa;
        qa.Bh[0] = wqh; qa.Bl[0] = wql; qa.bias[0] = bq; qa.Oh[0] = q16; qa.Ol[0] = nullptr;
        qa.Bh[1] = wkh; qa.Bl[1] = wkl; qa.bias[1] = bk; qa.Oh[1] = kh;  qa.Ol[1] = kl;
        qa.Bh[2] = wvh; qa.Bl[2] = wvl; qa.bias[2] = bv; qa.Oh[2] = v16; qa.Ol[2] = nullptr;
        qkv_gemm<<<dim3(24, MR/128), 128, GSM3>>>(xh, qa, MR, DD);
    }
    attn_tc<<<dim3(SS/128, NG), 256, AT_SMEM>>>(q16, kh, kl, v16,
                                                mask, btab, att16);
    tcgemm2<<<dim3(DD/128, MR/128), 128, GSM2>>>(att16, woh, wol, bo, tmp,
                                                 nullptr, MR, DD, DD, 0);
    ln_kernel<<<MR, 256>>>((const float4*)tmp, (const float4*)x,
                           (const float4*)ln1g, (const float4*)ln1b,
                           (float4*)h, h16);
    tcgemm2<<<dim3(FF/128, MR/128), 128, GSM2>>>(h16, w1h, w1l, b1, nullptr,
                                                 f16, MR, FF, DD, 1);
    tcgemm2<<<dim3(DD/128, MR/128), 128, GSM2>>>(f16, w2h, w2l, b2, tmp,
                                                 nullptr, MR, DD, FF, 0);
    ln_kernel<<<MR, 256>>>((const float4*)tmp, (const float4*)h,
                           (const float4*)ln2g, (const float4*)ln2b,
                           (float4*)out, nullptr);
}